// round 3
// baseline (speedup 1.0000x reference)
#include <cuda_runtime.h>
#include <cstdint>
#include <cstddef>

#define B_TOT 4096
#define NTOK  49
#define DIM   128
#define NH    4
#define HD    32
#define NW    64
#define SCALE 0.17677669529663687f   // 32^-0.5

// ---------------- device scratch (allowed: __device__ globals) ----------------
// packed tf32 weight fragments, fragment-linear so each warp B-load is coalesced
__device__ float g_wqkv[16 * 48 * 64];             // [kt][jt][reg*32+lane]
__device__ float g_wproj[16 * 16 * 64];
__device__ float g_bm[NW * NH * NTOK * NTOK];      // bias(rel_pos) + mask, combined

// ---------------- helpers ----------------
__device__ __forceinline__ uint32_t f2tf32(float x) {
    uint32_t r;
    asm("cvt.rna.tf32.f32 %0, %1;" : "=r"(r) : "f"(x));
    return r;
}

__device__ __forceinline__ void mma_tf32(float c[4],
                                         uint32_t a0, uint32_t a1, uint32_t a2, uint32_t a3,
                                         uint32_t b0, uint32_t b1) {
    asm volatile(
        "mma.sync.aligned.m16n8k8.row.col.f32.tf32.tf32.f32 "
        "{%0,%1,%2,%3}, {%4,%5,%6,%7}, {%8,%9}, {%0,%1,%2,%3};\n"
        : "+f"(c[0]), "+f"(c[1]), "+f"(c[2]), "+f"(c[3])
        : "r"(a0), "r"(a1), "r"(a2), "r"(a3), "r"(b0), "r"(b1));
}

// ---------------- prep kernels (tiny; run every launch, deterministic) --------
__global__ void pack_w_kernel(const float* __restrict__ qkv_w,
                              const float* __restrict__ proj_w) {
    int idx = blockIdx.x * blockDim.x + threadIdx.x;
    if (idx < 16 * 48 * 64) {
        int kt = idx / (48 * 64);
        int jt = (idx / 64) % 48;
        int p  = idx % 64;
        int reg = p >> 5, lane = p & 31;
        int krow = kt * 8 + (lane & 3) + reg * 4;
        int jcol = jt * 8 + (lane >> 2);
        g_wqkv[idx] = __uint_as_float(f2tf32(qkv_w[jcol * DIM + krow]));
    }
    if (idx < 16 * 16 * 64) {
        int kt = idx / (16 * 64);
        int jt = (idx / 64) % 16;
        int p  = idx % 64;
        int reg = p >> 5, lane = p & 31;
        int krow = kt * 8 + (lane & 3) + reg * 4;
        int jcol = jt * 8 + (lane >> 2);
        g_wproj[idx] = __uint_as_float(f2tf32(proj_w[jcol * DIM + krow]));
    }
}

__global__ void pack_bm_kernel(const float* __restrict__ mask,
                               const float* __restrict__ rpb,
                               const int*   __restrict__ rel_index) {
    int idx = blockIdx.x * blockDim.x + threadIdx.x;
    const int total = NW * NH * NTOK * NTOK;
    if (idx >= total) return;
    int r = idx % (NTOK * NTOK);
    int h = (idx / (NTOK * NTOK)) % NH;
    int w = idx / (NH * NTOK * NTOK);
    g_bm[idx] = rpb[rel_index[r] * NH + h] + mask[w * NTOK * NTOK + r];
}

// ---------------- fused main kernel: one CTA per window ----------------
// smem (floats): xs[64][132] (x, later attnout)  @0     (8448)
//                qs[4][64][36]                   @8448  (9216)
//                ks[4][64][36]                   @17664 (9216)
//                vs[4][64][40]                   @26880 (10240)
//                Ss[64][60]                      @37120 (3840)
// total 40960 floats = 163840 bytes
#define SMEM_FLOATS 40960

extern __shared__ float smem[];

__global__ void __launch_bounds__(256, 1)
win_attn_kernel(const float* __restrict__ x,
                const float* __restrict__ qkv_b,
                const float* __restrict__ proj_b,
                float* __restrict__ out) {
    const int b    = blockIdx.x;
    const int tid  = threadIdx.x;
    const int warp = tid >> 5;
    const int lane = tid & 31;
    const int g    = lane >> 2;   // group id (0..7)
    const int tg   = lane & 3;    // thread in group (0..3)

    float* xs = smem;             // stride 132
    float* qs = smem + 8448;      // stride 36
    float* ks = smem + 17664;     // stride 36
    float* vs = smem + 26880;     // stride 40
    float* Ss = smem + 37120;     // stride 60

    // zero q/k/v (pad rows must be exact 0 so 0*pad in attention stays finite)
    for (int i = tid; i < 9216 * 2 + 10240; i += 256) qs[i] = 0.f;

    // load x tile (tf32-rounded)
    const float* xb = x + (size_t)b * (NTOK * DIM);
    for (int i = tid; i < NTOK * DIM; i += 256) {
        int r = i >> 7, c = i & 127;
        xs[r * 132 + c] = __uint_as_float(f2tf32(xb[i]));
    }
    __syncthreads();

    // ---------- GEMM1: qkv[64x384] = xs[64x128] @ qkv_w^T ----------
    #pragma unroll
    for (int pass = 0; pass < 2; ++pass) {
        const int jt0 = warp * 6 + pass * 3;
        float acc[4][3][4];
        #pragma unroll
        for (int m = 0; m < 4; m++)
            #pragma unroll
            for (int j = 0; j < 3; j++)
                #pragma unroll
                for (int r = 0; r < 4; r++) acc[m][j][r] = 0.f;

        #pragma unroll
        for (int kt = 0; kt < 16; ++kt) {
            uint32_t af[4][4];
            #pragma unroll
            for (int m = 0; m < 4; m++) {
                int row = m * 16 + g;
                int col = kt * 8 + tg;
                af[m][0] = __float_as_uint(xs[row * 132 + col]);
                af[m][1] = __float_as_uint(xs[(row + 8) * 132 + col]);
                af[m][2] = __float_as_uint(xs[row * 132 + col + 4]);
                af[m][3] = __float_as_uint(xs[(row + 8) * 132 + col + 4]);
            }
            #pragma unroll
            for (int j = 0; j < 3; j++) {
                const float* bp = g_wqkv + (size_t)(kt * 48 + jt0 + j) * 64;
                uint32_t b0 = __float_as_uint(bp[lane]);
                uint32_t b1 = __float_as_uint(bp[32 + lane]);
                #pragma unroll
                for (int m = 0; m < 4; m++)
                    mma_tf32(acc[m][j], af[m][0], af[m][1], af[m][2], af[m][3], b0, b1);
            }
        }
        // scatter C into q/k/v smem (q pre-scaled, all tf32-rounded)
        #pragma unroll
        for (int j = 0; j < 3; j++) {
            int jt     = jt0 + j;
            int jbase  = jt * 8;
            int tensor = jbase >> 7;     // 0=q 1=k 2=v
            int j2     = jbase & 127;
            int h      = j2 >> 5;
            float* dst = (tensor == 0) ? qs : (tensor == 1) ? ks : vs;
            int stride = (tensor == 2) ? 40 : 36;
            int dbase  = (j2 & 31) + tg * 2;
            float bias0 = __ldg(qkv_b + jbase + tg * 2);
            float bias1 = __ldg(qkv_b + jbase + tg * 2 + 1);
            float scl = (tensor == 0) ? SCALE : 1.f;
            #pragma unroll
            for (int m = 0; m < 4; m++) {
                int row = m * 16 + g;
                if (row < NTOK) {
                    dst[(h * 64 + row) * stride + dbase]     = __uint_as_float(f2tf32((acc[m][j][0] + bias0) * scl));
                    dst[(h * 64 + row) * stride + dbase + 1] = __uint_as_float(f2tf32((acc[m][j][1] + bias1) * scl));
                }
                if (row + 8 < NTOK) {
                    dst[(h * 64 + row + 8) * stride + dbase]     = __uint_as_float(f2tf32((acc[m][j][2] + bias0) * scl));
                    dst[(h * 64 + row + 8) * stride + dbase + 1] = __uint_as_float(f2tf32((acc[m][j][3] + bias1) * scl));
                }
            }
        }
    }
    __syncthreads();

    // ---------- attention per head ----------
    const float* bmh_base = g_bm + (size_t)(b & (NW - 1)) * (NH * NTOK * NTOK);

    for (int h = 0; h < NH; ++h) {
        float* qh = qs + h * 2304;
        float* kh = ks + h * 2304;
        float* vh = vs + h * 2560;

        // S[64x56] = q[64x32] @ k^T ; warps 0..6 take one 8-col jtile each
        if (warp < 7) {
            const int jt = warp;
            float acc[4][4];
            #pragma unroll
            for (int m = 0; m < 4; m++)
                #pragma unroll
                for (int r = 0; r < 4; r++) acc[m][r] = 0.f;
            #pragma unroll
            for (int kt = 0; kt < 4; ++kt) {
                int d0 = kt * 8;
                uint32_t b0 = __float_as_uint(kh[(jt * 8 + g) * 36 + d0 + tg]);
                uint32_t b1 = __float_as_uint(kh[(jt * 8 + g) * 36 + d0 + tg + 4]);
                #pragma unroll
                for (int m = 0; m < 4; m++) {
                    int row = m * 16 + g;
                    uint32_t a0 = __float_as_uint(qh[row * 36 + d0 + tg]);
                    uint32_t a1 = __float_as_uint(qh[(row + 8) * 36 + d0 + tg]);
                    uint32_t a2 = __float_as_uint(qh[row * 36 + d0 + tg + 4]);
                    uint32_t a3 = __float_as_uint(qh[(row + 8) * 36 + d0 + tg + 4]);
                    mma_tf32(acc[m], a0, a1, a2, a3, b0, b1);
                }
            }
            #pragma unroll
            for (int m = 0; m < 4; m++) {
                int row = m * 16 + g;
                int c0  = jt * 8 + tg * 2;
                Ss[row * 60 + c0]           = acc[m][0];
                Ss[row * 60 + c0 + 1]       = acc[m][1];
                Ss[(row + 8) * 60 + c0]     = acc[m][2];
                Ss[(row + 8) * 60 + c0 + 1] = acc[m][3];
            }
        }
        __syncthreads();

        // softmax rows 0..48 with fused (bias+mask); write P tf32, pad cols = 0
        {
            const float* bmh = bmh_base + h * (NTOK * NTOK);
            for (int row = warp; row < NTOK; row += 8) {
                int j1 = lane, j2 = lane + 32;
                float v1 = Ss[row * 60 + j1] + bmh[row * NTOK + j1];
                float v2 = (j2 < NTOK) ? (Ss[row * 60 + j2] + bmh[row * NTOK + j2]) : -1e30f;
                float mx = fmaxf(v1, v2);
                #pragma unroll
                for (int o = 16; o > 0; o >>= 1) mx = fmaxf(mx, __shfl_xor_sync(0xffffffffu, mx, o));
                float e1 = __expf(v1 - mx);
                float e2 = (j2 < NTOK) ? __expf(v2 - mx) : 0.f;
                float sm = e1 + e2;
                #pragma unroll
                for (int o = 16; o > 0; o >>= 1) sm += __shfl_xor_sync(0xffffffffu, sm, o);
                float inv = 1.f / sm;
                Ss[row * 60 + j1] = __uint_as_float(f2tf32(e1 * inv));
                if (j2 < 56) Ss[row * 60 + j2] = __uint_as_float(f2tf32(e2 * inv));
            }
        }
        __syncthreads();

        // attnout_h[64x32] = P[64x56] @ v[56x32] -> xs cols [h*32, h*32+32)
        {
            const int mt  = warp & 3;
            const int jt0 = (warp >> 2) * 2;
            float acc[2][4];
            #pragma unroll
            for (int j = 0; j < 2; j++)
                #pragma unroll
                for (int r = 0; r < 4; r++) acc[j][r] = 0.f;
            #pragma unroll
            for (int kt = 0; kt < 7; ++kt) {
                int k0  = kt * 8;
                int row = mt * 16 + g;
                uint32_t a0 = __float_as_uint(Ss[row * 60 + k0 + tg]);
                uint32_t a1 = __float_as_uint(Ss[(row + 8) * 60 + k0 + tg]);
                uint32_t a2 = __float_as_uint(Ss[row * 60 + k0 + tg + 4]);
                uint32_t a3 = __float_as_uint(Ss[(row + 8) * 60 + k0 + tg + 4]);
                #pragma unroll
                for (int j = 0; j < 2; j++) {
                    int jt = jt0 + j;
                    uint32_t b0 = __float_as_uint(vh[(k0 + tg) * 40 + jt * 8 + g]);
                    uint32_t b1 = __float_as_uint(vh[(k0 + tg + 4) * 40 + jt * 8 + g]);
                    mma_tf32(acc[j], a0, a1, a2, a3, b0, b1);
                }
            }
            #pragma unroll
            for (int j = 0; j < 2; j++) {
                int col = h * 32 + (jt0 + j) * 8 + tg * 2;
                int row = mt * 16 + g;
                xs[row * 132 + col]           = __uint_as_float(f2tf32(acc[j][0]));
                xs[row * 132 + col + 1]       = __uint_as_float(f2tf32(acc[j][1]));
                xs[(row + 8) * 132 + col]     = __uint_as_float(f2tf32(acc[j][2]));
                xs[(row + 8) * 132 + col + 1] = __uint_as_float(f2tf32(acc[j][3]));
            }
        }
        __syncthreads();
    }

    // ---------- GEMM3: out[64x128] = attnout @ proj_w^T + proj_b ----------
    {
        const int jt0 = warp * 2;
        float acc[4][2][4];
        #pragma unroll
        for (int m = 0; m < 4; m++)
            #pragma unroll
            for (int j = 0; j < 2; j++)
                #pragma unroll
                for (int r = 0; r < 4; r++) acc[m][j][r] = 0.f;

        #pragma unroll
        for (int kt = 0; kt < 16; ++kt) {
            uint32_t af[4][4];
            #pragma unroll
            for (int m = 0; m < 4; m++) {
                int row = m * 16 + g;
                int col = kt * 8 + tg;
                af[m][0] = __float_as_uint(xs[row * 132 + col]);
                af[m][1] = __float_as_uint(xs[(row + 8) * 132 + col]);
                af[m][2] = __float_as_uint(xs[row * 132 + col + 4]);
                af[m][3] = __float_as_uint(xs[(row + 8) * 132 + col + 4]);
            }
            #pragma unroll
            for (int j = 0; j < 2; j++) {
                const float* bp = g_wproj + (size_t)(kt * 16 + jt0 + j) * 64;
                uint32_t b0 = __float_as_uint(bp[lane]);
                uint32_t b1 = __float_as_uint(bp[32 + lane]);
                #pragma unroll
                for (int m = 0; m < 4; m++)
                    mma_tf32(acc[m][j], af[m][0], af[m][1], af[m][2], af[m][3], b0, b1);
            }
        }

        float* ob = out + (size_t)b * (NTOK * DIM);
        #pragma unroll
        for (int j = 0; j < 2; j++) {
            int c0 = (jt0 + j) * 8 + tg * 2;
            float pb0 = __ldg(proj_b + c0);
            float pb1 = __ldg(proj_b + c0 + 1);
            #pragma unroll
            for (int m = 0; m < 4; m++) {
                int row = m * 16 + g;
                if (row < NTOK) {
                    float2 v; v.x = acc[m][j][0] + pb0; v.y = acc[m][j][1] + pb1;
                    *(float2*)(ob + row * DIM + c0) = v;
                }
                if (row + 8 < NTOK) {
                    float2 v; v.x = acc[m][j][2] + pb0; v.y = acc[m][j][3] + pb1;
                    *(float2*)(ob + (row + 8) * DIM + c0) = v;
                }
            }
        }
    }
}

// ---------------- launch ----------------
extern "C" void kernel_launch(void* const* d_in, const int* in_sizes, int n_in,
                              void* d_out, int out_size) {
    const float* x       = (const float*)d_in[0];
    const float* mask    = (const float*)d_in[1];
    const float* qkv_w   = (const float*)d_in[2];
    const float* qkv_b   = (const float*)d_in[3];
    const float* rpb     = (const float*)d_in[4];
    const float* proj_w  = (const float*)d_in[5];
    const float* proj_b  = (const float*)d_in[6];
    const int*   rel_idx = (const int*)d_in[7];
    float* out = (float*)d_out;

    pack_w_kernel<<<(16 * 48 * 64 + 255) / 256, 256>>>(qkv_w, proj_w);
    pack_bm_kernel<<<(NW * NH * NTOK * NTOK + 255) / 256, 256>>>(mask, rpb, rel_idx);

    cudaFuncSetAttribute(win_attn_kernel,
                         cudaFuncAttributeMaxDynamicSharedMemorySize,
                         SMEM_FLOATS * sizeof(float));
    win_attn_kernel<<<B_TOT, 256, SMEM_FLOATS * sizeof(float)>>>(x, qkv_b, proj_b, out);
}

// round 5
// speedup vs baseline: 1.1412x; 1.1412x over previous
#include <cuda_runtime.h>
#include <cstdint>
#include <cstddef>

#define B_TOT 4096
#define NTOK  49
#define DIM   128
#define NH    4
#define HD    32
#define NW    64
#define SCALE 0.17677669529663687f   // 32^-0.5

// ---------------- device scratch ----------------
__device__ float g_wqkv[16 * 48 * 64];             // [kt][jt][reg*32+lane] tf32
__device__ float g_wproj[16 * 16 * 64];
__device__ float g_bm[NW * NH * NTOK * NTOK];      // bias(rel_pos) + mask

// ---------------- helpers ----------------
__device__ __forceinline__ uint32_t f2tf32(float x) {
    uint32_t r;
    asm("cvt.rna.tf32.f32 %0, %1;" : "=r"(r) : "f"(x));
    return r;
}

__device__ __forceinline__ void mma_tf32(float c[4],
                                         uint32_t a0, uint32_t a1, uint32_t a2, uint32_t a3,
                                         uint32_t b0, uint32_t b1) {
    asm volatile(
        "mma.sync.aligned.m16n8k8.row.col.f32.tf32.tf32.f32 "
        "{%0,%1,%2,%3}, {%4,%5,%6,%7}, {%8,%9}, {%0,%1,%2,%3};\n"
        : "+f"(c[0]), "+f"(c[1]), "+f"(c[2]), "+f"(c[3])
        : "r"(a0), "r"(a1), "r"(a2), "r"(a3), "r"(b0), "r"(b1));
}

// fragment-linear index for a 64x128 tf32 A-operand:
// element (r,c) -> ((kt*4+m)*32 + lane)*4 + reg, so one LDS.128 per (kt,m,lane)
__device__ __forceinline__ int frag_idx(int r, int c) {
    int kt   = c >> 3;
    int m    = r >> 4;
    int lane = (r & 7) * 4 + (c & 3);
    int reg  = ((r >> 3) & 1) + (((c >> 2) & 1) << 1);
    return ((kt * 4 + m) * 32 + lane) * 4 + reg;
}

// ---------------- prep kernels ----------------
__global__ void pack_w_kernel(const float* __restrict__ qkv_w,
                              const float* __restrict__ proj_w) {
    int idx = blockIdx.x * blockDim.x + threadIdx.x;
    if (idx < 16 * 48 * 64) {
        int kt = idx / (48 * 64);
        int jt = (idx / 64) % 48;
        int p  = idx % 64;
        int reg = p >> 5, lane = p & 31;
        int krow = kt * 8 + (lane & 3) + reg * 4;
        int jcol = jt * 8 + (lane >> 2);
        g_wqkv[idx] = __uint_as_float(f2tf32(qkv_w[jcol * DIM + krow]));
    }
    if (idx < 16 * 16 * 64) {
        int kt = idx / (16 * 64);
        int jt = (idx / 64) % 16;
        int p  = idx % 64;
        int reg = p >> 5, lane = p & 31;
        int krow = kt * 8 + (lane & 3) + reg * 4;
        int jcol = jt * 8 + (lane >> 2);
        g_wproj[idx] = __uint_as_float(f2tf32(proj_w[jcol * DIM + krow]));
    }
}

__global__ void pack_bm_kernel(const float* __restrict__ mask,
                               const float* __restrict__ rpb,
                               const int*   __restrict__ rel_index) {
    int idx = blockIdx.x * blockDim.x + threadIdx.x;
    const int total = NW * NH * NTOK * NTOK;
    if (idx >= total) return;
    int r = idx % (NTOK * NTOK);
    int h = (idx / (NTOK * NTOK)) % NH;
    int w = idx / (NH * NTOK * NTOK);
    g_bm[idx] = rpb[rel_index[r] * NH + h] + mask[w * NTOK * NTOK + r];
}

// ---------------- fused main kernel: one CTA per window, 512 threads ----------
// smem (floats): xfrag[8192] @0        (x, later attnout, fragment-linear)
//                qs[4][64][36] @8192
//                ks[4][64][36] @17408
//                vs[4][64][40] @26624
//                Ss[4][64][60] @36864
// total 52224 floats = 208896 bytes
#define SMEM_FLOATS 52224

extern __shared__ float smem[];

__global__ void __launch_bounds__(512, 1)
win_attn_kernel(const float* __restrict__ x,
                const float* __restrict__ qkv_b,
                const float* __restrict__ proj_b,
                float* __restrict__ out) {
    const int b    = blockIdx.x;
    const int tid  = threadIdx.x;
    const int warp = tid >> 5;
    const int lane = tid & 31;
    const int g    = lane >> 2;
    const int tg   = lane & 3;

    float* xfrag = smem;
    float* qs    = smem + 8192;   // stride 36, per-head 2304
    float* ks    = smem + 17408;
    float* vs    = smem + 26624;  // stride 40, per-head 2560
    float* Ss    = smem + 36864;  // stride 60, per-head 3840

    // zero xfrag + q/k/v (pads must be exact 0); 36864 floats = 9216 float4
    {
        float4 z = make_float4(0.f, 0.f, 0.f, 0.f);
        float4* p = (float4*)smem;
        #pragma unroll
        for (int i = tid; i < 9216; i += 512) p[i] = z;
    }
    __syncthreads();

    // load x into fragment-linear layout (tf32-rounded)
    const float* xb = x + (size_t)b * (NTOK * DIM);
    for (int i = tid; i < NTOK * DIM; i += 512) {
        int r = i >> 7, c = i & 127;
        xfrag[frag_idx(r, c)] = __uint_as_float(f2tf32(xb[i]));
    }
    __syncthreads();

    // ---------- GEMM1: qkv[64x384] = x[64x128] @ qkv_w^T, 3 jtiles/warp ------
    {
        const int jt0 = warp * 3;
        float acc[4][3][4];
        #pragma unroll
        for (int m = 0; m < 4; m++)
            #pragma unroll
            for (int j = 0; j < 3; j++)
                #pragma unroll
                for (int r = 0; r < 4; r++) acc[m][j][r] = 0.f;

        #pragma unroll
        for (int kt = 0; kt < 16; ++kt) {
            uint32_t af[4][4];
            #pragma unroll
            for (int m = 0; m < 4; m++) {
                float4 a = *(const float4*)(xfrag + ((kt * 4 + m) * 32 + lane) * 4);
                af[m][0] = __float_as_uint(a.x);
                af[m][1] = __float_as_uint(a.y);
                af[m][2] = __float_as_uint(a.z);
                af[m][3] = __float_as_uint(a.w);
            }
            #pragma unroll
            for (int j = 0; j < 3; j++) {
                const float* bp = g_wqkv + (size_t)(kt * 48 + jt0 + j) * 64;
                uint32_t b0 = __float_as_uint(__ldg(bp + lane));
                uint32_t b1 = __float_as_uint(__ldg(bp + 32 + lane));
                #pragma unroll
                for (int m = 0; m < 4; m++)
                    mma_tf32(acc[m][j], af[m][0], af[m][1], af[m][2], af[m][3], b0, b1);
            }
        }
        #pragma unroll
        for (int j = 0; j < 3; j++) {
            int jt     = jt0 + j;
            int jbase  = jt * 8;
            int tensor = jbase >> 7;     // 0=q 1=k 2=v
            int j2     = jbase & 127;
            int h      = j2 >> 5;
            float* dst = (tensor == 0) ? qs : (tensor == 1) ? ks : vs;
            int stride = (tensor == 2) ? 40 : 36;
            int dbase  = (j2 & 31) + tg * 2;
            float bias0 = __ldg(qkv_b + jbase + tg * 2);
            float bias1 = __ldg(qkv_b + jbase + tg * 2 + 1);
            float scl = (tensor == 0) ? SCALE : 1.f;
            #pragma unroll
            for (int m = 0; m < 4; m++) {
                int row = m * 16 + g;
                if (row < NTOK) {
                    dst[(h * 64 + row) * stride + dbase]     = __uint_as_float(f2tf32((acc[m][j][0] + bias0) * scl));
                    dst[(h * 64 + row) * stride + dbase + 1] = __uint_as_float(f2tf32((acc[m][j][1] + bias1) * scl));
                }
                if (row + 8 < NTOK) {
                    dst[(h * 64 + row + 8) * stride + dbase]     = __uint_as_float(f2tf32((acc[m][j][2] + bias0) * scl));
                    dst[(h * 64 + row + 8) * stride + dbase + 1] = __uint_as_float(f2tf32((acc[m][j][3] + bias1) * scl));
                }
            }
        }
    }
    __syncthreads();

    // ---------- S = q @ k^T for ALL heads (4 warps/head) ----------
    {
        const int h  = warp >> 2;
        const int wh = warp & 3;
        float* qh = qs + h * 2304;
        float* kh = ks + h * 2304;
        float* Sh = Ss + h * 3840;

        float acc[2][4][4];
        #pragma unroll
        for (int jj = 0; jj < 2; jj++)
            #pragma unroll
            for (int m = 0; m < 4; m++)
                #pragma unroll
                for (int r = 0; r < 4; r++) acc[jj][m][r] = 0.f;

        #pragma unroll
        for (int kt = 0; kt < 4; ++kt) {
            int d0 = kt * 8;
            uint32_t af[4][4];
            #pragma unroll
            for (int m = 0; m < 4; m++) {
                int row = m * 16 + g;
                af[m][0] = __float_as_uint(qh[row * 36 + d0 + tg]);
                af[m][1] = __float_as_uint(qh[(row + 8) * 36 + d0 + tg]);
                af[m][2] = __float_as_uint(qh[row * 36 + d0 + tg + 4]);
                af[m][3] = __float_as_uint(qh[(row + 8) * 36 + d0 + tg + 4]);
            }
            #pragma unroll
            for (int jj = 0; jj < 2; jj++) {
                int jt = wh + jj * 4;
                if (jt < 7) {
                    uint32_t b0 = __float_as_uint(kh[(jt * 8 + g) * 36 + d0 + tg]);
                    uint32_t b1 = __float_as_uint(kh[(jt * 8 + g) * 36 + d0 + tg + 4]);
                    #pragma unroll
                    for (int m = 0; m < 4; m++)
                        mma_tf32(acc[jj][m], af[m][0], af[m][1], af[m][2], af[m][3], b0, b1);
                }
            }
        }
        #pragma unroll
        for (int jj = 0; jj < 2; jj++) {
            int jt = wh + jj * 4;
            if (jt < 7) {
                #pragma unroll
                for (int m = 0; m < 4; m++) {
                    int row = m * 16 + g;
                    int c0  = jt * 8 + tg * 2;
                    Sh[row * 60 + c0]           = acc[jj][m][0];
                    Sh[row * 60 + c0 + 1]       = acc[jj][m][1];
                    Sh[(row + 8) * 60 + c0]     = acc[jj][m][2];
                    Sh[(row + 8) * 60 + c0 + 1] = acc[jj][m][3];
                }
            }
        }
    }
    __syncthreads();

    // ---------- softmax: all heads, 196 rows over 16 warps ----------
    {
        const float* bm0 = g_bm + (size_t)(b & (NW - 1)) * (NH * NTOK * NTOK);
        for (int hr = warp; hr < NH * NTOK; hr += 16) {
            int h   = hr / NTOK;
            int row = hr - h * NTOK;
            float* Sh = Ss + h * 3840 + row * 60;
            const float* bmh = bm0 + h * (NTOK * NTOK) + row * NTOK;
            int j1 = lane, j2 = lane + 32;
            float v1 = Sh[j1] + __ldg(bmh + j1);
            float v2 = (j2 < NTOK) ? (Sh[j2] + __ldg(bmh + j2)) : -1e30f;
            float mx = fmaxf(v1, v2);
            #pragma unroll
            for (int o = 16; o > 0; o >>= 1) mx = fmaxf(mx, __shfl_xor_sync(0xffffffffu, mx, o));
            float e1 = __expf(v1 - mx);
            float e2 = (j2 < NTOK) ? __expf(v2 - mx) : 0.f;
            float sm = e1 + e2;
            #pragma unroll
            for (int o = 16; o > 0; o >>= 1) sm += __shfl_xor_sync(0xffffffffu, sm, o);
            float inv = 1.f / sm;
            Sh[j1] = __uint_as_float(f2tf32(e1 * inv));
            if (j2 < 56) Sh[j2] = __uint_as_float(f2tf32(e2 * inv));
        }
    }
    __syncthreads();

    // ---------- PV: attnout = P @ v, all heads (4 warps/head, 1 jtile/warp) ---
    {
        const int h  = warp >> 2;
        const int jt = warp & 3;
        float* vh = vs + h * 2560;
        float* Sh = Ss + h * 3840;

        float acc[4][4];
        #pragma unroll
        for (int m = 0; m < 4; m++)
            #pragma unroll
            for (int r = 0; r < 4; r++) acc[m][r] = 0.f;

        #pragma unroll
        for (int kt = 0; kt < 7; ++kt) {
            int k0 = kt * 8;
            uint32_t b0 = __float_as_uint(vh[(k0 + tg) * 40 + jt * 8 + g]);
            uint32_t b1 = __float_as_uint(vh[(k0 + tg + 4) * 40 + jt * 8 + g]);
            #pragma unroll
            for (int m = 0; m < 4; m++) {
                int row = m * 16 + g;
                uint32_t a0 = __float_as_uint(Sh[row * 60 + k0 + tg]);
                uint32_t a1 = __float_as_uint(Sh[(row + 8) * 60 + k0 + tg]);
                uint32_t a2 = __float_as_uint(Sh[row * 60 + k0 + tg + 4]);
                uint32_t a3 = __float_as_uint(Sh[(row + 8) * 60 + k0 + tg + 4]);
                mma_tf32(acc[m], a0, a1, a2, a3, b0, b1);
            }
        }
        // scatter into fragment-linear attnout (reuses xfrag)
        int c0 = h * 32 + jt * 8 + tg * 2;
        #pragma unroll
        for (int m = 0; m < 4; m++) {
            int row = m * 16 + g;
            xfrag[frag_idx(row, c0)]         = __uint_as_float(f2tf32(acc[m][0]));
            xfrag[frag_idx(row, c0 + 1)]     = __uint_as_float(f2tf32(acc[m][1]));
            xfrag[frag_idx(row + 8, c0)]     = __uint_as_float(f2tf32(acc[m][2]));
            xfrag[frag_idx(row + 8, c0 + 1)] = __uint_as_float(f2tf32(acc[m][3]));
        }
    }
    __syncthreads();

    // ---------- GEMM3: out = attnout @ proj_w^T + proj_b, 1 jtile/warp -------
    {
        const int jt = warp;
        float acc[4][4];
        #pragma unroll
        for (int m = 0; m < 4; m++)
            #pragma unroll
            for (int r = 0; r < 4; r++) acc[m][r] = 0.f;

        #pragma unroll
        for (int kt = 0; kt < 16; ++kt) {
            const float* bp = g_wproj + (size_t)(kt * 16 + jt) * 64;
            uint32_t b0 = __float_as_uint(__ldg(bp + lane));
            uint32_t b1 = __float_as_uint(__ldg(bp + 32 + lane));
            #pragma unroll
            for (int m = 0; m < 4; m++) {
                float4 a = *(const float4*)(xfrag + ((kt * 4 + m) * 32 + lane) * 4);
                mma_tf32(acc[m], __float_as_uint(a.x), __float_as_uint(a.y),
                                 __float_as_uint(a.z), __float_as_uint(a.w), b0, b1);
            }
        }

        float* ob = out + (size_t)b * (NTOK * DIM);
        int c0 = jt * 8 + tg * 2;
        float pb0 = __ldg(proj_b + c0);
        float pb1 = __ldg(proj_b + c0 + 1);
        #pragma unroll
        for (int m = 0; m < 4; m++) {
            int row = m * 16 + g;
            if (row < NTOK) {
                float2 v; v.x = acc[m][0] + pb0; v.y = acc[m][1] + pb1;
                *(float2*)(ob + row * DIM + c0) = v;
            }
            if (row + 8 < NTOK) {
                float2 v; v.x = acc[m][2] + pb0; v.y = acc[m][3] + pb1;
                *(float2*)(ob + (row + 8) * DIM + c0) = v;
            }
        }
    }
}

// ---------------- launch ----------------
extern "C" void kernel_launch(void* const* d_in, const int* in_sizes, int n_in,
                              void* d_out, int out_size) {
    const float* x       = (const float*)d_in[0];
    const float* mask    = (const float*)d_in[1];
    const float* qkv_w   = (const float*)d_in[2];
    const float* qkv_b   = (const float*)d_in[3];
    const float* rpb     = (const float*)d_in[4];
    const float* proj_w  = (const float*)d_in[5];
    const float* proj_b  = (const float*)d_in[6];
    const int*   rel_idx = (const int*)d_in[7];
    float* out = (float*)d_out;

    pack_w_kernel<<<(16 * 48 * 64 + 255) / 256, 256>>>(qkv_w, proj_w);
    pack_bm_kernel<<<(NW * NH * NTOK * NTOK + 255) / 256, 256>>>(mask, rpb, rel_idx);

    cudaFuncSetAttribute(win_attn_kernel,
                         cudaFuncAttributeMaxDynamicSharedMemorySize,
                         SMEM_FLOATS * sizeof(float));
    win_attn_kernel<<<B_TOT, 512, SMEM_FLOATS * sizeof(float)>>>(x, qkv_b, proj_b, out);
}

// round 6
// speedup vs baseline: 1.6044x; 1.4059x over previous
#include <cuda_runtime.h>
#include <cuda_fp16.h>
#include <cstdint>
#include <cstddef>

#define B_TOT 4096
#define NTOK  49
#define DIM   128
#define NH    4
#define HD    32
#define NW    64
#define SCALE 0.17677669529663687f   // 32^-0.5

// ---------------- device scratch ----------------
// fp16 weight B-fragments: per (kt, jt, lane) -> uint2 {b0, b1} (each = fp16x2)
__device__ uint2 g_wqkv16[8 * 48 * 32];
__device__ uint2 g_wproj16[8 * 16 * 32];
__device__ float g_bm[NW * NH * NTOK * NTOK];      // bias(rel_pos) + mask

// ---------------- helpers ----------------
__device__ __forceinline__ uint32_t pack_h2(float a, float b) {
    __half2 h = __floats2half2_rn(a, b);
    return *reinterpret_cast<uint32_t*>(&h);
}

__device__ __forceinline__ void mma_f16(float c[4],
                                        uint32_t a0, uint32_t a1, uint32_t a2, uint32_t a3,
                                        uint32_t b0, uint32_t b1) {
    asm volatile(
        "mma.sync.aligned.m16n8k16.row.col.f32.f16.f16.f32 "
        "{%0,%1,%2,%3}, {%4,%5,%6,%7}, {%8,%9}, {%0,%1,%2,%3};\n"
        : "+f"(c[0]), "+f"(c[1]), "+f"(c[2]), "+f"(c[3])
        : "r"(a0), "r"(a1), "r"(a2), "r"(a3), "r"(b0), "r"(b1));
}

// ---------------- prep kernels ----------------
__global__ void pack_w_kernel(const float* __restrict__ qkv_w,
                              const float* __restrict__ proj_w) {
    int idx = blockIdx.x * blockDim.x + threadIdx.x;
    if (idx < 8 * 48 * 32) {
        int kt   = idx / (48 * 32);
        int jt   = (idx / 32) % 48;
        int lane = idx % 32;
        int n    = jt * 8 + (lane >> 2);
        int k0   = kt * 16 + (lane & 3) * 2;
        uint2 v;
        v.x = pack_h2(qkv_w[n * DIM + k0],     qkv_w[n * DIM + k0 + 1]);
        v.y = pack_h2(qkv_w[n * DIM + k0 + 8], qkv_w[n * DIM + k0 + 9]);
        g_wqkv16[idx] = v;
    }
    if (idx < 8 * 16 * 32) {
        int kt   = idx / (16 * 32);
        int jt   = (idx / 32) % 16;
        int lane = idx % 32;
        int n    = jt * 8 + (lane >> 2);
        int k0   = kt * 16 + (lane & 3) * 2;
        uint2 v;
        v.x = pack_h2(proj_w[n * DIM + k0],     proj_w[n * DIM + k0 + 1]);
        v.y = pack_h2(proj_w[n * DIM + k0 + 8], proj_w[n * DIM + k0 + 9]);
        g_wproj16[idx] = v;
    }
}

__global__ void pack_bm_kernel(const float* __restrict__ mask,
                               const float* __restrict__ rpb,
                               const int*   __restrict__ rel_index) {
    int idx = blockIdx.x * blockDim.x + threadIdx.x;
    const int total = NW * NH * NTOK * NTOK;
    if (idx >= total) return;
    int r = idx % (NTOK * NTOK);
    int h = (idx / (NTOK * NTOK)) % NH;
    int w = idx / (NH * NTOK * NTOK);
    g_bm[idx] = rpb[rel_index[r] * NH + h] + mask[w * NTOK * NTOK + r];
}

// ---------------- smem layout (uint32 units) ----------------
// XF @0      : 4096  x / attnout, A-frag-linear fp16  [64x128]
// QF @4096   : 4096  q per head, A-frag-linear fp16   [64x32] x4
// KF @8192   : 4096  k per head, B-frag-linear fp16   [n=64 tok][k=32 dim] x4
// VF @12288  : 4096  v per head, B-frag-linear fp16   [k=64 tok][n=32 dim] x4
// PF @16384  : 8192  P per head, A-frag-linear fp16   [64x64] x4
// SS @24576  : 15360 S scores fp32, [64][60] x4
#define XF 0
#define QF 4096
#define KF 8192
#define VF 12288
#define PF 16384
#define SS 24576
#define SMEM_U32 39936    // 159744 bytes

extern __shared__ uint32_t smem_u32[];

__global__ void __launch_bounds__(512, 1)
win_attn_kernel(const float* __restrict__ x,
                const float* __restrict__ qkv_b,
                const float* __restrict__ proj_b,
                float* __restrict__ out) {
    const int b    = blockIdx.x;
    const int tid  = threadIdx.x;
    const int warp = tid >> 5;
    const int lane = tid & 31;
    const int g    = lane >> 2;
    const int tg   = lane & 3;

    uint32_t* sm    = smem_u32;
    float*    Ssf   = reinterpret_cast<float*>(smem_u32 + SS);
    char*     smb   = reinterpret_cast<char*>(smem_u32);

    // zero XF..PF end (24576 u32 = 6144 uint4); covers xfrag pads + P pads
    {
        uint4 z = make_uint4(0u, 0u, 0u, 0u);
        uint4* p = reinterpret_cast<uint4*>(sm);
        #pragma unroll
        for (int i = tid; i < 6144; i += 512) p[i] = z;
    }
    __syncthreads();

    // load x into A-frag-linear fp16 (pairs of adjacent cols)
    const float* xb = x + (size_t)b * (NTOK * DIM);
    for (int i = tid; i < NTOK * (DIM / 2); i += 512) {
        int r  = i / 64;
        int c2 = i - r * 64;
        int c  = c2 * 2;
        float2 v = *(const float2*)(xb + r * DIM + c);
        int kt   = c >> 4;
        int m    = r >> 4;
        int ln   = (r & 7) * 4 + (c2 & 3);
        int reg  = ((r >> 3) & 1) | (((c >> 3) & 1) << 1);
        sm[XF + ((kt * 4 + m) * 32 + ln) * 4 + reg] = pack_h2(v.x, v.y);
    }
    __syncthreads();

    // ---------- GEMM1: qkv[64x384] = x @ qkv_w^T, 3 jtiles/warp, fp16 mma ----
    {
        const int jt0 = warp * 3;
        float acc[4][3][4];
        #pragma unroll
        for (int m = 0; m < 4; m++)
            #pragma unroll
            for (int j = 0; j < 3; j++)
                #pragma unroll
                for (int r = 0; r < 4; r++) acc[m][j][r] = 0.f;

        #pragma unroll
        for (int kt = 0; kt < 8; ++kt) {
            uint4 af[4];
            #pragma unroll
            for (int m = 0; m < 4; m++)
                af[m] = *(const uint4*)(sm + XF + ((kt * 4 + m) * 32 + lane) * 4);
            #pragma unroll
            for (int j = 0; j < 3; j++) {
                uint2 bw = __ldg(&g_wqkv16[(kt * 48 + jt0 + j) * 32 + lane]);
                #pragma unroll
                for (int m = 0; m < 4; m++)
                    mma_f16(acc[m][j], af[m].x, af[m].y, af[m].z, af[m].w, bw.x, bw.y);
            }
        }

        // epilogue: bias, (scale), convert fp16, scatter to q/k/v frag layouts
        #pragma unroll
        for (int j = 0; j < 3; j++) {
            int jt     = jt0 + j;
            int jbase  = jt * 8;
            int tensor = jbase >> 7;       // 0=q 1=k 2=v
            int j2     = jbase & 127;
            int h      = j2 >> 5;
            int cl     = (j2 & 31) + tg * 2;   // head-local dim of c0
            float b0f  = __ldg(qkv_b + jbase + tg * 2);
            float b1f  = __ldg(qkv_b + jbase + tg * 2 + 1);

            if (tensor == 0) {
                int ktq  = cl >> 4;
                int regc = (cl >> 3) & 1;
                #pragma unroll
                for (int m = 0; m < 4; m++) {
                    uint32_t base = QF + h * 1024 + ((ktq * 4 + m) * 32 + lane) * 4;
                    sm[base + (regc << 1)]     = pack_h2((acc[m][j][0] + b0f) * SCALE,
                                                         (acc[m][j][1] + b1f) * SCALE);
                    sm[base + 1 + (regc << 1)] = pack_h2((acc[m][j][2] + b0f) * SCALE,
                                                         (acc[m][j][3] + b1f) * SCALE);
                }
            } else if (tensor == 1) {
                int ktk = cl >> 4;
                int reg = (cl >> 3) & 1;
                #pragma unroll
                for (int m = 0; m < 4; m++) {
                    // token rows t = m*16+g (nt=2m), t+8 (nt=2m+1); lane' == lane
                    sm[KF + h * 1024 + ((ktk * 8 + 2 * m) * 32 + lane) * 2 + reg] =
                        pack_h2(acc[m][j][0] + b0f, acc[m][j][1] + b1f);
                    sm[KF + h * 1024 + ((ktk * 8 + 2 * m + 1) * 32 + lane) * 2 + reg] =
                        pack_h2(acc[m][j][2] + b0f, acc[m][j][3] + b1f);
                }
            } else {
                // v: scalar fp16 stores into [k=token][n=dim] B-frag layout
                #pragma unroll
                for (int m = 0; m < 4; m++) {
                    #pragma unroll
                    for (int rs = 0; rs < 2; rs++) {
                        int t = m * 16 + g + 8 * rs;
                        #pragma unroll
                        for (int cs = 0; cs < 2; cs++) {
                            int   d   = cl + cs;
                            float val = acc[m][j][rs * 2 + cs] + (cs ? b1f : b0f);
                            int ktv = t >> 4;
                            int nt  = d >> 3;
                            int ln  = (d & 7) * 4 + ((t & 7) >> 1);
                            int reg = (t >> 3) & 1;
                            uint32_t slot = VF + h * 1024 + ((ktv * 4 + nt) * 32 + ln) * 2 + reg;
                            *reinterpret_cast<__half*>(smb + slot * 4 + (t & 1) * 2) =
                                __float2half_rn(val);
                        }
                    }
                }
            }
        }
    }
    __syncthreads();

    // ---------- S = q @ k^T, all heads (4 warps/head, jt = wh, wh+4) ----------
    {
        const int h  = warp >> 2;
        const int wh = warp & 3;

        float acc[2][4][4];
        #pragma unroll
        for (int jj = 0; jj < 2; jj++)
            #pragma unroll
            for (int m = 0; m < 4; m++)
                #pragma unroll
                for (int r = 0; r < 4; r++) acc[jj][m][r] = 0.f;

        #pragma unroll
        for (int kt = 0; kt < 2; ++kt) {
            uint4 af[4];
            #pragma unroll
            for (int m = 0; m < 4; m++)
                af[m] = *(const uint4*)(sm + QF + h * 1024 + ((kt * 4 + m) * 32 + lane) * 4);
            #pragma unroll
            for (int jj = 0; jj < 2; jj++) {
                int jt = wh + jj * 4;
                uint2 bw = *(const uint2*)(sm + KF + h * 1024 + ((kt * 8 + jt) * 32 + lane) * 2);
                #pragma unroll
                for (int m = 0; m < 4; m++)
                    mma_f16(acc[jj][m], af[m].x, af[m].y, af[m].z, af[m].w, bw.x, bw.y);
            }
        }
        #pragma unroll
        for (int jj = 0; jj < 2; jj++) {
            int jt = wh + jj * 4;
            if (jt < 7) {
                #pragma unroll
                for (int m = 0; m < 4; m++) {
                    int row = m * 16 + g;
                    int c0  = jt * 8 + tg * 2;
                    float* Sh = Ssf + h * 3840;
                    Sh[row * 60 + c0]           = acc[jj][m][0];
                    Sh[row * 60 + c0 + 1]       = acc[jj][m][1];
                    Sh[(row + 8) * 60 + c0]     = acc[jj][m][2];
                    Sh[(row + 8) * 60 + c0 + 1] = acc[jj][m][3];
                }
            }
        }
    }
    __syncthreads();

    // ---------- softmax: 196 rows over 16 warps; P -> fp16 A-frag layout ------
    {
        const float* bm0 = g_bm + (size_t)(b & (NW - 1)) * (NH * NTOK * NTOK);
        for (int hr = warp; hr < NH * NTOK; hr += 16) {
            int h   = hr / NTOK;
            int row = hr - h * NTOK;
            float* Sh = Ssf + h * 3840 + row * 60;
            const float* bmh = bm0 + h * (NTOK * NTOK) + row * NTOK;
            int j1 = lane, j2 = lane + 32;
            float v1 = Sh[j1] + __ldg(bmh + j1);
            float v2 = (j2 < NTOK) ? (Sh[j2] + __ldg(bmh + j2)) : -1e30f;
            float mx = fmaxf(v1, v2);
            #pragma unroll
            for (int o = 16; o > 0; o >>= 1) mx = fmaxf(mx, __shfl_xor_sync(0xffffffffu, mx, o));
            float e1 = __expf(v1 - mx);
            float e2 = (j2 < NTOK) ? __expf(v2 - mx) : 0.f;
            float sm_ = e1 + e2;
            #pragma unroll
            for (int o = 16; o > 0; o >>= 1) sm_ += __shfl_xor_sync(0xffffffffu, sm_, o);
            float inv = 1.f / sm_;
            // store P[row][c] as fp16 into A-frag-linear layout
            {
                int c = j1, kt = c >> 4, m = row >> 4;
                int ln  = (row & 7) * 4 + ((c & 7) >> 1);
                int reg = ((row >> 3) & 1) | (((c >> 3) & 1) << 1);
                uint32_t slot = PF + h * 2048 + ((kt * 4 + m) * 32 + ln) * 4 + reg;
                *reinterpret_cast<__half*>(smb + slot * 4 + (c & 1) * 2) = __float2half_rn(e1 * inv);
            }
            if (j2 < 56) {
                int c = j2, kt = c >> 4, m = row >> 4;
                int ln  = (row & 7) * 4 + ((c & 7) >> 1);
                int reg = ((row >> 3) & 1) | (((c >> 3) & 1) << 1);
                uint32_t slot = PF + h * 2048 + ((kt * 4 + m) * 32 + ln) * 4 + reg;
                *reinterpret_cast<__half*>(smb + slot * 4 + (c & 1) * 2) = __float2half_rn(e2 * inv);
            }
        }
    }
    __syncthreads();

    // ---------- PV: attnout = P @ v (4 warps/head, 1 ntile/warp) --------------
    {
        const int h  = warp >> 2;
        const int jt = warp & 3;

        float acc[4][4];
        #pragma unroll
        for (int m = 0; m < 4; m++)
            #pragma unroll
            for (int r = 0; r < 4; r++) acc[m][r] = 0.f;

        #pragma unroll
        for (int kt = 0; kt < 4; ++kt) {
            uint2 bw = *(const uint2*)(sm + VF + h * 1024 + ((kt * 4 + jt) * 32 + lane) * 2);
            #pragma unroll
            for (int m = 0; m < 4; m++) {
                uint4 af = *(const uint4*)(sm + PF + h * 2048 + ((kt * 4 + m) * 32 + lane) * 4);
                mma_f16(acc[m], af.x, af.y, af.z, af.w, bw.x, bw.y);
            }
        }
        // scatter into A-frag-linear attnout (reuses XF)
        int cg   = h * 32 + jt * 8 + tg * 2;
        int ktx  = cg >> 4;
        int regc = (cg >> 3) & 1;
        #pragma unroll
        for (int m = 0; m < 4; m++) {
            uint32_t base = XF + ((ktx * 4 + m) * 32 + lane) * 4;
            sm[base + (regc << 1)]     = pack_h2(acc[m][0], acc[m][1]);
            sm[base + 1 + (regc << 1)] = pack_h2(acc[m][2], acc[m][3]);
        }
    }
    __syncthreads();

    // ---------- GEMM3: out = attnout @ proj_w^T + proj_b, 1 jtile/warp -------
    {
        const int jt = warp;
        float acc[4][4];
        #pragma unroll
        for (int m = 0; m < 4; m++)
            #pragma unroll
            for (int r = 0; r < 4; r++) acc[m][r] = 0.f;

        #pragma unroll
        for (int kt = 0; kt < 8; ++kt) {
            uint2 bw = __ldg(&g_wproj16[(kt * 16 + jt) * 32 + lane]);
            #pragma unroll
            for (int m = 0; m < 4; m++) {
                uint4 af = *(const uint4*)(sm + XF + ((kt * 4 + m) * 32 + lane) * 4);
                mma_f16(acc[m], af.x, af.y, af.z, af.w, bw.x, bw.y);
            }
        }

        float* ob = out + (size_t)b * (NTOK * DIM);
        int c0 = jt * 8 + tg * 2;
        float pb0 = __ldg(proj_b + c0);
        float pb1 = __ldg(proj_b + c0 + 1);
        #pragma unroll
        for (int m = 0; m < 4; m++) {
            int row = m * 16 + g;
            if (row < NTOK) {
                float2 v; v.x = acc[m][0] + pb0; v.y = acc[m][1] + pb1;
                *(float2*)(ob + row * DIM + c0) = v;
            }
            if (row + 8 < NTOK) {
                float2 v; v.x = acc[m][2] + pb0; v.y = acc[m][3] + pb1;
                *(float2*)(ob + (row + 8) * DIM + c0) = v;
            }
        }
    }
}

// ---------------- launch ----------------
extern "C" void kernel_launch(void* const* d_in, const int* in_sizes, int n_in,
                              void* d_out, int out_size) {
    const float* x       = (const float*)d_in[0];
    const float* mask    = (const float*)d_in[1];
    const float* qkv_w   = (const float*)d_in[2];
    const float* qkv_b   = (const float*)d_in[3];
    const float* rpb     = (const float*)d_in[4];
    const float* proj_w  = (const float*)d_in[5];
    const float* proj_b  = (const float*)d_in[6];
    const int*   rel_idx = (const int*)d_in[7];
    float* out = (float*)d_out;

    pack_w_kernel<<<(8 * 48 * 32 + 255) / 256, 256>>>(qkv_w, proj_w);
    pack_bm_kernel<<<(NW * NH * NTOK * NTOK + 255) / 256, 256>>>(mask, rpb, rel_idx);

    cudaFuncSetAttribute(win_attn_kernel,
                         cudaFuncAttributeMaxDynamicSharedMemorySize,
                         SMEM_U32 * sizeof(uint32_t));
    win_attn_kernel<<<B_TOT, 512, SMEM_U32 * sizeof(uint32_t)>>>(x, qkv_b, proj_b, out);
}

// round 8
// speedup vs baseline: 2.5924x; 1.6158x over previous
#include <cuda_runtime.h>
#include <cuda_fp16.h>
#include <cstdint>
#include <cstddef>

#define B_TOT 4096
#define NTOK  49
#define DIM   128
#define NH    4
#define HD    32
#define NW    64
#define SCALE 0.17677669529663687f   // 32^-0.5

// ---------------- device scratch ----------------
// fp16 weight B-fragments: per (kt, jt, lane) -> uint2 {b0, b1} (each = fp16x2)
__device__ uint2 g_wqkv16[8 * 48 * 32];
__device__ uint2 g_wproj16[8 * 16 * 32];
// bias+mask, padded: [NW][NH][64 rows][56 cols]; cols>=49 = -1e30, rows>=49 = 0
#define BM_R 64
#define BM_C 56
__device__ float g_bm[NW * NH * BM_R * BM_C];

// ---------------- helpers ----------------
__device__ __forceinline__ uint32_t pack_h2(float a, float b) {
    __half2 h = __floats2half2_rn(a, b);
    return *reinterpret_cast<uint32_t*>(&h);
}

__device__ __forceinline__ void mma_f16(float c[4],
                                        uint32_t a0, uint32_t a1, uint32_t a2, uint32_t a3,
                                        uint32_t b0, uint32_t b1) {
    asm volatile(
        "mma.sync.aligned.m16n8k16.row.col.f32.f16.f16.f32 "
        "{%0,%1,%2,%3}, {%4,%5,%6,%7}, {%8,%9}, {%0,%1,%2,%3};\n"
        : "+f"(c[0]), "+f"(c[1]), "+f"(c[2]), "+f"(c[3])
        : "r"(a0), "r"(a1), "r"(a2), "r"(a3), "r"(b0), "r"(b1));
}

// ---------------- prep kernels ----------------
__global__ void pack_w_kernel(const float* __restrict__ qkv_w,
                              const float* __restrict__ proj_w) {
    int idx = blockIdx.x * blockDim.x + threadIdx.x;
    if (idx < 8 * 48 * 32) {
        int kt   = idx / (48 * 32);
        int jt   = (idx / 32) % 48;
        int lane = idx % 32;
        int n    = jt * 8 + (lane >> 2);
        int k0   = kt * 16 + (lane & 3) * 2;
        uint2 v;
        v.x = pack_h2(qkv_w[n * DIM + k0],     qkv_w[n * DIM + k0 + 1]);
        v.y = pack_h2(qkv_w[n * DIM + k0 + 8], qkv_w[n * DIM + k0 + 9]);
        g_wqkv16[idx] = v;
    }
    if (idx < 8 * 16 * 32) {
        int kt   = idx / (16 * 32);
        int jt   = (idx / 32) % 16;
        int lane = idx % 32;
        int n    = jt * 8 + (lane >> 2);
        int k0   = kt * 16 + (lane & 3) * 2;
        uint2 v;
        v.x = pack_h2(proj_w[n * DIM + k0],     proj_w[n * DIM + k0 + 1]);
        v.y = pack_h2(proj_w[n * DIM + k0 + 8], proj_w[n * DIM + k0 + 9]);
        g_wproj16[idx] = v;
    }
}

__global__ void pack_bm_kernel(const float* __restrict__ mask,
                               const float* __restrict__ rpb,
                               const int*   __restrict__ rel_index) {
    int idx = blockIdx.x * blockDim.x + threadIdx.x;
    const int total = NW * NH * BM_R * BM_C;
    if (idx >= total) return;
    int col = idx % BM_C;
    int row = (idx / BM_C) % BM_R;
    int h   = (idx / (BM_C * BM_R)) % NH;
    int w   = idx / (BM_C * BM_R * NH);
    float v;
    if (row < NTOK && col < NTOK) {
        int r = row * NTOK + col;
        v = rpb[rel_index[r] * NH + h] + mask[w * NTOK * NTOK + r];
    } else if (row < NTOK) {
        v = -1e30f;        // pad column: exp -> 0
    } else {
        v = 0.f;           // pad row: discarded later
    }
    g_bm[idx] = v;
}

// ---------------- smem layout (uint32 units) ----------------
// XF @0      : 4096  x / attnout, A-frag-linear fp16  [64x128]
// QF @4096   : 4096  q per head, A-frag-linear fp16   [64x32] x4
// KF @8192   : 4096  k per head, B-frag-linear fp16   [n=64 tok][k=32 dim] x4
// VF @12288  : 4096  v per head, B-frag-linear fp16   [k=64 tok][n=32 dim] x4
#define XF 0
#define QF 4096
#define KF 8192
#define VF 12288
#define SMEM_U32 16384    // 65536 bytes

extern __shared__ uint32_t smem_u32[];

__global__ void __launch_bounds__(512, 1)
win_attn_kernel(const float* __restrict__ x,
                const float* __restrict__ qkv_b,
                const float* __restrict__ proj_b,
                float* __restrict__ out) {
    const int b    = blockIdx.x;
    const int tid  = threadIdx.x;
    const int warp = tid >> 5;
    const int lane = tid & 31;
    const int g    = lane >> 2;
    const int tg   = lane & 3;

    uint32_t* sm  = smem_u32;
    char*     smb = reinterpret_cast<char*>(smem_u32);

    // zero XF (pad-row fragments must be exact 0): 4096 u32 = 1024 uint4
    {
        uint4 z = make_uint4(0u, 0u, 0u, 0u);
        uint4* p = reinterpret_cast<uint4*>(sm);
        #pragma unroll
        for (int i = tid; i < 1024; i += 512) p[i] = z;
    }
    __syncthreads();

    // load x into A-frag-linear fp16 (pairs of adjacent cols)
    const float* xb = x + (size_t)b * (NTOK * DIM);
    for (int i = tid; i < NTOK * (DIM / 2); i += 512) {
        int r  = i / 64;
        int c2 = i - r * 64;
        int c  = c2 * 2;
        float2 v = *(const float2*)(xb + r * DIM + c);
        int kt   = c >> 4;
        int m    = r >> 4;
        int ln   = (r & 7) * 4 + (c2 & 3);
        int reg  = ((r >> 3) & 1) | (((c >> 3) & 1) << 1);
        sm[XF + ((kt * 4 + m) * 32 + ln) * 4 + reg] = pack_h2(v.x, v.y);
    }
    __syncthreads();

    // ---------- GEMM1: qkv[64x384] = x @ qkv_w^T, 3 jtiles/warp, fp16 mma ----
    {
        const int jt0 = warp * 3;
        float acc[4][3][4];
        #pragma unroll
        for (int m = 0; m < 4; m++)
            #pragma unroll
            for (int j = 0; j < 3; j++)
                #pragma unroll
                for (int r = 0; r < 4; r++) acc[m][j][r] = 0.f;

        #pragma unroll
        for (int kt = 0; kt < 8; ++kt) {
            uint4 af[4];
            #pragma unroll
            for (int m = 0; m < 4; m++)
                af[m] = *(const uint4*)(sm + XF + ((kt * 4 + m) * 32 + lane) * 4);
            #pragma unroll
            for (int j = 0; j < 3; j++) {
                uint2 bw = __ldg(&g_wqkv16[(kt * 48 + jt0 + j) * 32 + lane]);
                #pragma unroll
                for (int m = 0; m < 4; m++)
                    mma_f16(acc[m][j], af[m].x, af[m].y, af[m].z, af[m].w, bw.x, bw.y);
            }
        }

        // epilogue: bias, (scale), convert fp16, scatter to q/k/v frag layouts
        #pragma unroll
        for (int j = 0; j < 3; j++) {
            int jt     = jt0 + j;
            int jbase  = jt * 8;
            int tensor = jbase >> 7;       // 0=q 1=k 2=v
            int j2     = jbase & 127;
            int h      = j2 >> 5;
            int cl     = (j2 & 31) + tg * 2;   // head-local dim of c0
            float b0f  = __ldg(qkv_b + jbase + tg * 2);
            float b1f  = __ldg(qkv_b + jbase + tg * 2 + 1);

            if (tensor == 0) {
                int ktq  = cl >> 4;
                int regc = (cl >> 3) & 1;
                #pragma unroll
                for (int m = 0; m < 4; m++) {
                    uint32_t base = QF + h * 1024 + ((ktq * 4 + m) * 32 + lane) * 4;
                    sm[base + (regc << 1)]     = pack_h2((acc[m][j][0] + b0f) * SCALE,
                                                         (acc[m][j][1] + b1f) * SCALE);
                    sm[base + 1 + (regc << 1)] = pack_h2((acc[m][j][2] + b0f) * SCALE,
                                                         (acc[m][j][3] + b1f) * SCALE);
                }
            } else if (tensor == 1) {
                int ktk = cl >> 4;
                int reg = (cl >> 3) & 1;
                #pragma unroll
                for (int m = 0; m < 4; m++) {
                    sm[KF + h * 1024 + ((ktk * 8 + 2 * m) * 32 + lane) * 2 + reg] =
                        pack_h2(acc[m][j][0] + b0f, acc[m][j][1] + b1f);
                    sm[KF + h * 1024 + ((ktk * 8 + 2 * m + 1) * 32 + lane) * 2 + reg] =
                        pack_h2(acc[m][j][2] + b0f, acc[m][j][3] + b1f);
                }
            } else {
                // v: scalar fp16 stores into [k=token][n=dim] B-frag layout
                #pragma unroll
                for (int m = 0; m < 4; m++) {
                    #pragma unroll
                    for (int rs = 0; rs < 2; rs++) {
                        int t = m * 16 + g + 8 * rs;
                        #pragma unroll
                        for (int cs = 0; cs < 2; cs++) {
                            int   d   = cl + cs;
                            float val = acc[m][j][rs * 2 + cs] + (cs ? b1f : b0f);
                            int ktv = t >> 4;
                            int nt  = d >> 3;
                            int ln  = (d & 7) * 4 + ((t & 7) >> 1);
                            int reg = (t >> 3) & 1;
                            uint32_t slot = VF + h * 1024 + ((ktv * 4 + nt) * 32 + ln) * 2 + reg;
                            *reinterpret_cast<__half*>(smb + slot * 4 + (t & 1) * 2) =
                                __float2half_rn(val);
                        }
                    }
                }
            }
        }
    }
    __syncthreads();

    // ---------- fused S = q@k^T -> softmax -> PV, all in registers ----------
    // warp = (head, m-tile): owns 16 complete score rows.
    {
        const int h  = warp >> 2;
        const int mt = warp & 3;

        // S: acc[jt][0..1] = rows r0, cols jt*8+2tg+{0,1}; [2..3] = row r0+8
        float acc[7][4];
        #pragma unroll
        for (int jt = 0; jt < 7; jt++)
            #pragma unroll
            for (int r = 0; r < 4; r++) acc[jt][r] = 0.f;

        #pragma unroll
        for (int kt = 0; kt < 2; ++kt) {
            uint4 af = *(const uint4*)(sm + QF + h * 1024 + ((kt * 4 + mt) * 32 + lane) * 4);
            #pragma unroll
            for (int jt = 0; jt < 7; ++jt) {
                uint2 bw = *(const uint2*)(sm + KF + h * 1024 + ((kt * 8 + jt) * 32 + lane) * 2);
                mma_f16(acc[jt], af.x, af.y, af.z, af.w, bw.x, bw.y);
            }
        }

        // bias + mask (pad cols arrive as -1e30 from the table)
        const int r0 = mt * 16 + g;
        const float* bm = g_bm + ((size_t)(b & (NW - 1)) * NH + h) * (BM_R * BM_C);
        #pragma unroll
        for (int jt = 0; jt < 7; ++jt) {
            int c0 = jt * 8 + tg * 2;
            float2 bv0 = __ldg((const float2*)(bm + r0 * BM_C + c0));
            float2 bv1 = __ldg((const float2*)(bm + (r0 + 8) * BM_C + c0));
            acc[jt][0] += bv0.x; acc[jt][1] += bv0.y;
            acc[jt][2] += bv1.x; acc[jt][3] += bv1.y;
        }

        // row-wise softmax: reduce 14 locals + 2 shuffles over the tg quartet
        float mx0 = -1e30f, mx1 = -1e30f;
        #pragma unroll
        for (int jt = 0; jt < 7; ++jt) {
            mx0 = fmaxf(mx0, fmaxf(acc[jt][0], acc[jt][1]));
            mx1 = fmaxf(mx1, fmaxf(acc[jt][2], acc[jt][3]));
        }
        #pragma unroll
        for (int o = 1; o <= 2; o <<= 1) {
            mx0 = fmaxf(mx0, __shfl_xor_sync(0xffffffffu, mx0, o));
            mx1 = fmaxf(mx1, __shfl_xor_sync(0xffffffffu, mx1, o));
        }
        float s0 = 0.f, s1 = 0.f;
        #pragma unroll
        for (int jt = 0; jt < 7; ++jt) {
            acc[jt][0] = __expf(acc[jt][0] - mx0); s0 += acc[jt][0];
            acc[jt][1] = __expf(acc[jt][1] - mx0); s0 += acc[jt][1];
            acc[jt][2] = __expf(acc[jt][2] - mx1); s1 += acc[jt][2];
            acc[jt][3] = __expf(acc[jt][3] - mx1); s1 += acc[jt][3];
        }
        #pragma unroll
        for (int o = 1; o <= 2; o <<= 1) {
            s0 += __shfl_xor_sync(0xffffffffu, s0, o);
            s1 += __shfl_xor_sync(0xffffffffu, s1, o);
        }
        float i0 = 1.f / s0, i1 = 1.f / s1;

        // P -> fp16 pairs; S C-layout == PV A-layout, so no smem round-trip
        uint32_t ph[7][2];
        #pragma unroll
        for (int jt = 0; jt < 7; ++jt) {
            ph[jt][0] = pack_h2(acc[jt][0] * i0, acc[jt][1] * i0);
            ph[jt][1] = pack_h2(acc[jt][2] * i1, acc[jt][3] * i1);
        }

        // PV: attnout[16 x 32] = P[16 x 64pad] @ V[64pad x 32]
        float po[4][4];
        #pragma unroll
        for (int n = 0; n < 4; n++)
            #pragma unroll
            for (int r = 0; r < 4; r++) po[n][r] = 0.f;

        #pragma unroll
        for (int kt = 0; kt < 4; ++kt) {
            uint32_t a0 = ph[2 * kt][0], a1 = ph[2 * kt][1];
            uint32_t a2 = (kt < 3) ? ph[2 * kt + 1][0] : 0u;
            uint32_t a3 = (kt < 3) ? ph[2 * kt + 1][1] : 0u;
            #pragma unroll
            for (int n = 0; n < 4; ++n) {
                uint2 bw = *(const uint2*)(sm + VF + h * 1024 + ((kt * 4 + n) * 32 + lane) * 2);
                mma_f16(po[n], a0, a1, a2, a3, bw.x, bw.y);
            }
        }

        // scatter into A-frag-linear attnout (reuses XF)
        #pragma unroll
        for (int n = 0; n < 4; ++n) {
            int cg   = h * 32 + n * 8 + tg * 2;
            int ktx  = cg >> 4;
            int regc = (cg >> 3) & 1;
            uint32_t base = XF + ((ktx * 4 + mt) * 32 + lane) * 4;
            sm[base + (regc << 1)]     = pack_h2(po[n][0], po[n][1]);
            sm[base + 1 + (regc << 1)] = pack_h2(po[n][2], po[n][3]);
        }
    }
    __syncthreads();

    // ---------- GEMM3: out = attnout @ proj_w^T + proj_b, 1 jtile/warp -------
    {
        const int jt = warp;
        float acc[4][4];
        #pragma unroll
        for (int m = 0; m < 4; m++)
            #pragma unroll
            for (int r = 0; r < 4; r++) acc[m][r] = 0.f;

        #pragma unroll
        for (int kt = 0; kt < 8; ++kt) {
            uint2 bw = __ldg(&g_wproj16[(kt * 16 + jt) * 32 + lane]);
            #pragma unroll
            for (int m = 0; m < 4; m++) {
                uint4 af = *(const uint4*)(sm + XF + ((kt * 4 + m) * 32 + lane) * 4);
                mma_f16(acc[m], af.x, af.y, af.z, af.w, bw.x, bw.y);
            }
        }

        float* ob = out + (size_t)b * (NTOK * DIM);
        int c0 = jt * 8 + tg * 2;
        float pb0 = __ldg(proj_b + c0);
        float pb1 = __ldg(proj_b + c0 + 1);
        #pragma unroll
        for (int m = 0; m < 4; m++) {
            int row = m * 16 + g;
            if (row < NTOK) {
                float2 v; v.x = acc[m][0] + pb0; v.y = acc[m][1] + pb1;
                *(float2*)(ob + row * DIM + c0) = v;
            }
            if (row + 8 < NTOK) {
                float2 v; v.x = acc[m][2] + pb0; v.y = acc[m][3] + pb1;
                *(float2*)(ob + (row + 8) * DIM + c0) = v;
            }
        }
    }
}

// ---------------- launch ----------------
extern "C" void kernel_launch(void* const* d_in, const int* in_sizes, int n_in,
                              void* d_out, int out_size) {
    const float* x       = (const float*)d_in[0];
    const float* mask    = (const float*)d_in[1];
    const float* qkv_w   = (const float*)d_in[2];
    const float* qkv_b   = (const float*)d_in[3];
    const float* rpb     = (const float*)d_in[4];
    const float* proj_w  = (const float*)d_in[5];
    const float* proj_b  = (const float*)d_in[6];
    const int*   rel_idx = (const int*)d_in[7];
    float* out = (float*)d_out;

    pack_w_kernel<<<(8 * 48 * 32 + 255) / 256, 256>>>(qkv_w, proj_w);
    pack_bm_kernel<<<(NW * NH * BM_R * BM_C + 255) / 256, 256>>>(mask, rpb, rel_idx);

    cudaFuncSetAttribute(win_attn_kernel,
                         cudaFuncAttributeMaxDynamicSharedMemorySize,
                         SMEM_U32 * sizeof(uint32_t));
    win_attn_kernel<<<B_TOT, 512, SMEM_U32 * sizeof(uint32_t)>>>(x, qkv_b, proj_b, out);
}

// round 9
// speedup vs baseline: 4.1890x; 1.6159x over previous
#include <cuda_runtime.h>
#include <cuda_fp16.h>
#include <cstdint>
#include <cstddef>

#define B_TOT 4096
#define NTOK  49
#define DIM   128
#define NH    4
#define HD    32
#define NW    64
#define SCALE 0.17677669529663687f   // 32^-0.5

// ---------------- device scratch ----------------
// fp16 weight B-fragments: per (kt, jt, lane) -> uint2 {b0, b1} (each = fp16x2)
__device__ uint2 g_wqkv16[8 * 48 * 32];
__device__ uint2 g_wproj16[8 * 16 * 32];
// bias+mask, padded: [NW][NH][64 rows][56 cols]; cols>=49 = -1e30, rows>=49 = 0
#define BM_R 64
#define BM_C 56
__device__ float g_bm[NW * NH * BM_R * BM_C];

// ---------------- helpers ----------------
__device__ __forceinline__ uint32_t pack_h2(float a, float b) {
    __half2 h = __floats2half2_rn(a, b);
    return *reinterpret_cast<uint32_t*>(&h);
}

__device__ __forceinline__ void mma_f16(float c[4],
                                        uint32_t a0, uint32_t a1, uint32_t a2, uint32_t a3,
                                        uint32_t b0, uint32_t b1) {
    asm volatile(
        "mma.sync.aligned.m16n8k16.row.col.f32.f16.f16.f32 "
        "{%0,%1,%2,%3}, {%4,%5,%6,%7}, {%8,%9}, {%0,%1,%2,%3};\n"
        : "+f"(c[0]), "+f"(c[1]), "+f"(c[2]), "+f"(c[3])
        : "r"(a0), "r"(a1), "r"(a2), "r"(a3), "r"(b0), "r"(b1));
}

// ---------------- prep kernels ----------------
__global__ void pack_w_kernel(const float* __restrict__ qkv_w,
                              const float* __restrict__ proj_w) {
    int idx = blockIdx.x * blockDim.x + threadIdx.x;
    if (idx < 8 * 48 * 32) {
        int kt   = idx / (48 * 32);
        int jt   = (idx / 32) % 48;
        int lane = idx % 32;
        int n    = jt * 8 + (lane >> 2);
        int k0   = kt * 16 + (lane & 3) * 2;
        uint2 v;
        v.x = pack_h2(qkv_w[n * DIM + k0],     qkv_w[n * DIM + k0 + 1]);
        v.y = pack_h2(qkv_w[n * DIM + k0 + 8], qkv_w[n * DIM + k0 + 9]);
        g_wqkv16[idx] = v;
    }
    if (idx < 8 * 16 * 32) {
        int kt   = idx / (16 * 32);
        int jt   = (idx / 32) % 16;
        int lane = idx % 32;
        int n    = jt * 8 + (lane >> 2);
        int k0   = kt * 16 + (lane & 3) * 2;
        uint2 v;
        v.x = pack_h2(proj_w[n * DIM + k0],     proj_w[n * DIM + k0 + 1]);
        v.y = pack_h2(proj_w[n * DIM + k0 + 8], proj_w[n * DIM + k0 + 9]);
        g_wproj16[idx] = v;
    }
}

__global__ void pack_bm_kernel(const float* __restrict__ mask,
                               const float* __restrict__ rpb,
                               const int*   __restrict__ rel_index) {
    int idx = blockIdx.x * blockDim.x + threadIdx.x;
    const int total = NW * NH * BM_R * BM_C;
    if (idx >= total) return;
    int col = idx % BM_C;
    int row = (idx / BM_C) % BM_R;
    int h   = (idx / (BM_C * BM_R)) % NH;
    int w   = idx / (BM_C * BM_R * NH);
    float v;
    if (row < NTOK && col < NTOK) {
        int r = row * NTOK + col;
        v = rpb[rel_index[r] * NH + h] + mask[w * NTOK * NTOK + r];
    } else if (row < NTOK) {
        v = -1e30f;        // pad column: exp -> 0
    } else {
        v = 0.f;           // pad row: discarded later
    }
    g_bm[idx] = v;
}

// ---------------- smem layout (uint32 units) ----------------
// XF @0      : 4096  x / attnout, A-frag-linear fp16  [64x128]
// QF @4096   : 4096  q per head, A-frag-linear fp16   [64x32] x4
// KF @8192   : 4096  k per head, B-frag-linear fp16   [n=64 tok][k=32 dim] x4
// VF @12288  : 4096  v per head, B-frag-linear fp16   [k=64 tok][n=32 dim] x4
#define XF 0
#define QF 4096
#define KF 8192
#define VF 12288
#define SMEM_U32 16384    // 65536 bytes; x2 CTAs = 128 KB/SM

extern __shared__ uint32_t smem_u32[];

__global__ void __launch_bounds__(256, 2)
win_attn_kernel(const float* __restrict__ x,
                const float* __restrict__ qkv_b,
                const float* __restrict__ proj_b,
                float* __restrict__ out) {
    const int b    = blockIdx.x;
    const int tid  = threadIdx.x;
    const int warp = tid >> 5;       // 0..7
    const int lane = tid & 31;
    const int g    = lane >> 2;
    const int tg   = lane & 3;

    uint32_t* sm  = smem_u32;
    char*     smb = reinterpret_cast<char*>(smem_u32);

    // load x into A-frag-linear fp16; pad rows (>=49) written as zero directly
    const float* xb = x + (size_t)b * (NTOK * DIM);
    #pragma unroll
    for (int i = tid; i < 64 * 64; i += 256) {
        int r  = i >> 6;
        int c2 = i & 63;
        int c  = c2 * 2;
        uint32_t val = 0u;
        if (r < NTOK) {
            float2 v = *(const float2*)(xb + r * DIM + c);
            val = pack_h2(v.x, v.y);
        }
        int kt   = c >> 4;
        int m    = r >> 4;
        int ln   = (r & 7) * 4 + (c2 & 3);
        int reg  = ((r >> 3) & 1) | (((c >> 3) & 1) << 1);
        sm[XF + ((kt * 4 + m) * 32 + ln) * 4 + reg] = val;
    }
    __syncthreads();

    // ---------- GEMM1: qkv[64x384] = x @ qkv_w^T, 2 passes x 3 jtiles/warp ---
    #pragma unroll 1
    for (int pass = 0; pass < 2; ++pass) {
        const int jt0 = warp * 3 + pass * 24;
        float acc[4][3][4];
        #pragma unroll
        for (int m = 0; m < 4; m++)
            #pragma unroll
            for (int j = 0; j < 3; j++)
                #pragma unroll
                for (int r = 0; r < 4; r++) acc[m][j][r] = 0.f;

        #pragma unroll
        for (int kt = 0; kt < 8; ++kt) {
            uint4 af[4];
            #pragma unroll
            for (int m = 0; m < 4; m++)
                af[m] = *(const uint4*)(sm + XF + ((kt * 4 + m) * 32 + lane) * 4);
            #pragma unroll
            for (int j = 0; j < 3; j++) {
                uint2 bw = __ldg(&g_wqkv16[(kt * 48 + jt0 + j) * 32 + lane]);
                #pragma unroll
                for (int m = 0; m < 4; m++)
                    mma_f16(acc[m][j], af[m].x, af[m].y, af[m].z, af[m].w, bw.x, bw.y);
            }
        }

        // epilogue: bias, (scale), convert fp16, scatter to q/k/v frag layouts
        #pragma unroll
        for (int j = 0; j < 3; j++) {
            int jt     = jt0 + j;
            int jbase  = jt * 8;
            int tensor = jbase >> 7;       // 0=q 1=k 2=v
            int j2     = jbase & 127;
            int h      = j2 >> 5;
            int cl     = (j2 & 31) + tg * 2;   // head-local dim of c0
            float b0f  = __ldg(qkv_b + jbase + tg * 2);
            float b1f  = __ldg(qkv_b + jbase + tg * 2 + 1);

            if (tensor == 0) {
                int ktq  = cl >> 4;
                int regc = (cl >> 3) & 1;
                #pragma unroll
                for (int m = 0; m < 4; m++) {
                    uint32_t base = QF + h * 1024 + ((ktq * 4 + m) * 32 + lane) * 4;
                    sm[base + (regc << 1)]     = pack_h2((acc[m][j][0] + b0f) * SCALE,
                                                         (acc[m][j][1] + b1f) * SCALE);
                    sm[base + 1 + (regc << 1)] = pack_h2((acc[m][j][2] + b0f) * SCALE,
                                                         (acc[m][j][3] + b1f) * SCALE);
                }
            } else if (tensor == 1) {
                int ktk = cl >> 4;
                int reg = (cl >> 3) & 1;
                #pragma unroll
                for (int m = 0; m < 4; m++) {
                    sm[KF + h * 1024 + ((ktk * 8 + 2 * m) * 32 + lane) * 2 + reg] =
                        pack_h2(acc[m][j][0] + b0f, acc[m][j][1] + b1f);
                    sm[KF + h * 1024 + ((ktk * 8 + 2 * m + 1) * 32 + lane) * 2 + reg] =
                        pack_h2(acc[m][j][2] + b0f, acc[m][j][3] + b1f);
                }
            } else {
                // v: scalar fp16 stores into [k=token][n=dim] B-frag layout
                #pragma unroll
                for (int m = 0; m < 4; m++) {
                    #pragma unroll
                    for (int rs = 0; rs < 2; rs++) {
                        int t = m * 16 + g + 8 * rs;
                        #pragma unroll
                        for (int cs = 0; cs < 2; cs++) {
                            int   d   = cl + cs;
                            float val = acc[m][j][rs * 2 + cs] + (cs ? b1f : b0f);
                            int ktv = t >> 4;
                            int nt  = d >> 3;
                            int ln  = (d & 7) * 4 + ((t & 7) >> 1);
                            int reg = (t >> 3) & 1;
                            uint32_t slot = VF + h * 1024 + ((ktv * 4 + nt) * 32 + ln) * 2 + reg;
                            *reinterpret_cast<__half*>(smb + slot * 4 + (t & 1) * 2) =
                                __float2half_rn(val);
                        }
                    }
                }
            }
        }
    }
    __syncthreads();

    // ---------- fused S = q@k^T -> softmax -> PV, 2 units/warp ----------
    // unit u = (head h = u>>2, m-tile mt = u&3): 16 complete score rows.
    #pragma unroll 1
    for (int u = warp; u < 16; u += 8) {
        const int h  = u >> 2;
        const int mt = u & 3;

        // S: acc[jt][0..1] = rows r0, cols jt*8+2tg+{0,1}; [2..3] = row r0+8
        float acc[7][4];
        #pragma unroll
        for (int jt = 0; jt < 7; jt++)
            #pragma unroll
            for (int r = 0; r < 4; r++) acc[jt][r] = 0.f;

        #pragma unroll
        for (int kt = 0; kt < 2; ++kt) {
            uint4 af = *(const uint4*)(sm + QF + h * 1024 + ((kt * 4 + mt) * 32 + lane) * 4);
            #pragma unroll
            for (int jt = 0; jt < 7; ++jt) {
                uint2 bw = *(const uint2*)(sm + KF + h * 1024 + ((kt * 8 + jt) * 32 + lane) * 2);
                mma_f16(acc[jt], af.x, af.y, af.z, af.w, bw.x, bw.y);
            }
        }

        // bias + mask (pad cols arrive as -1e30 from the table)
        const int r0 = mt * 16 + g;
        const float* bm = g_bm + ((size_t)(b & (NW - 1)) * NH + h) * (BM_R * BM_C);
        #pragma unroll
        for (int jt = 0; jt < 7; ++jt) {
            int c0 = jt * 8 + tg * 2;
            float2 bv0 = __ldg((const float2*)(bm + r0 * BM_C + c0));
            float2 bv1 = __ldg((const float2*)(bm + (r0 + 8) * BM_C + c0));
            acc[jt][0] += bv0.x; acc[jt][1] += bv0.y;
            acc[jt][2] += bv1.x; acc[jt][3] += bv1.y;
        }

        // row-wise softmax: reduce 14 locals + 2 shuffles over the tg quartet
        float mx0 = -1e30f, mx1 = -1e30f;
        #pragma unroll
        for (int jt = 0; jt < 7; ++jt) {
            mx0 = fmaxf(mx0, fmaxf(acc[jt][0], acc[jt][1]));
            mx1 = fmaxf(mx1, fmaxf(acc[jt][2], acc[jt][3]));
        }
        #pragma unroll
        for (int o = 1; o <= 2; o <<= 1) {
            mx0 = fmaxf(mx0, __shfl_xor_sync(0xffffffffu, mx0, o));
            mx1 = fmaxf(mx1, __shfl_xor_sync(0xffffffffu, mx1, o));
        }
        float s0 = 0.f, s1 = 0.f;
        #pragma unroll
        for (int jt = 0; jt < 7; ++jt) {
            acc[jt][0] = __expf(acc[jt][0] - mx0); s0 += acc[jt][0];
            acc[jt][1] = __expf(acc[jt][1] - mx0); s0 += acc[jt][1];
            acc[jt][2] = __expf(acc[jt][2] - mx1); s1 += acc[jt][2];
            acc[jt][3] = __expf(acc[jt][3] - mx1); s1 += acc[jt][3];
        }
        #pragma unroll
        for (int o = 1; o <= 2; o <<= 1) {
            s0 += __shfl_xor_sync(0xffffffffu, s0, o);
            s1 += __shfl_xor_sync(0xffffffffu, s1, o);
        }
        float i0 = 1.f / s0, i1 = 1.f / s1;

        // P -> fp16 pairs; S C-layout == PV A-layout, so no smem round-trip
        uint32_t ph[7][2];
        #pragma unroll
        for (int jt = 0; jt < 7; ++jt) {
            ph[jt][0] = pack_h2(acc[jt][0] * i0, acc[jt][1] * i0);
            ph[jt][1] = pack_h2(acc[jt][2] * i1, acc[jt][3] * i1);
        }

        // PV: attnout[16 x 32] = P[16 x 64pad] @ V[64pad x 32]
        float po[4][4];
        #pragma unroll
        for (int n = 0; n < 4; n++)
            #pragma unroll
            for (int r = 0; r < 4; r++) po[n][r] = 0.f;

        #pragma unroll
        for (int kt = 0; kt < 4; ++kt) {
            uint32_t a0 = ph[2 * kt][0], a1 = ph[2 * kt][1];
            uint32_t a2 = (kt < 3) ? ph[2 * kt + 1][0] : 0u;
            uint32_t a3 = (kt < 3) ? ph[2 * kt + 1][1] : 0u;
            #pragma unroll
            for (int n = 0; n < 4; ++n) {
                uint2 bw = *(const uint2*)(sm + VF + h * 1024 + ((kt * 4 + n) * 32 + lane) * 2);
                mma_f16(po[n], a0, a1, a2, a3, bw.x, bw.y);
            }
        }

        // scatter into A-frag-linear attnout (reuses XF)
        #pragma unroll
        for (int n = 0; n < 4; ++n) {
            int cg   = h * 32 + n * 8 + tg * 2;
            int ktx  = cg >> 4;
            int regc = (cg >> 3) & 1;
            uint32_t base = XF + ((ktx * 4 + mt) * 32 + lane) * 4;
            sm[base + (regc << 1)]     = pack_h2(po[n][0], po[n][1]);
            sm[base + 1 + (regc << 1)] = pack_h2(po[n][2], po[n][3]);
        }
    }
    __syncthreads();

    // ---------- GEMM3: out = attnout @ proj_w^T + proj_b, 2 jtiles/warp ------
    {
        float acc[2][4][4];
        #pragma unroll
        for (int jj = 0; jj < 2; jj++)
            #pragma unroll
            for (int m = 0; m < 4; m++)
                #pragma unroll
                for (int r = 0; r < 4; r++) acc[jj][m][r] = 0.f;

        #pragma unroll
        for (int kt = 0; kt < 8; ++kt) {
            uint4 af[4];
            #pragma unroll
            for (int m = 0; m < 4; m++)
                af[m] = *(const uint4*)(sm + XF + ((kt * 4 + m) * 32 + lane) * 4);
            #pragma unroll
            for (int jj = 0; jj < 2; jj++) {
                int jt = warp + jj * 8;
                uint2 bw = __ldg(&g_wproj16[(kt * 16 + jt) * 32 + lane]);
                #pragma unroll
                for (int m = 0; m < 4; m++)
                    mma_f16(acc[jj][m], af[m].x, af[m].y, af[m].z, af[m].w, bw.x, bw.y);
            }
        }

        float* ob = out + (size_t)b * (NTOK * DIM);
        #pragma unroll
        for (int jj = 0; jj < 2; jj++) {
            int jt = warp + jj * 8;
            int c0 = jt * 8 + tg * 2;
            float pb0 = __ldg(proj_b + c0);
            float pb1 = __ldg(proj_b + c0 + 1);
            #pragma unroll
            for (int m = 0; m < 4; m++) {
                int row = m * 16 + g;
                if (row < NTOK) {
                    float2 v; v.x = acc[jj][m][0] + pb0; v.y = acc[jj][m][1] + pb1;
                    *(float2*)(ob + row * DIM + c0) = v;
                }
                if (row + 8 < NTOK) {
                    float2 v; v.x = acc[jj][m][2] + pb0; v.y = acc[jj][m][3] + pb1;
                    *(float2*)(ob + (row + 8) * DIM + c0) = v;
                }
            }
        }
    }
}

// ---------------- launch ----------------
extern "C" void kernel_launch(void* const* d_in, const int* in_sizes, int n_in,
                              void* d_out, int out_size) {
    const float* x       = (const float*)d_in[0];
    const float* mask    = (const float*)d_in[1];
    const float* qkv_w   = (const float*)d_in[2];
    const float* qkv_b   = (const float*)d_in[3];
    const float* rpb     = (const float*)d_in[4];
    const float* proj_w  = (const float*)d_in[5];
    const float* proj_b  = (const float*)d_in[6];
    const int*   rel_idx = (const int*)d_in[7];
    float* out = (float*)d_out;

    pack_w_kernel<<<(8 * 48 * 32 + 255) / 256, 256>>>(qkv_w, proj_w);
    pack_bm_kernel<<<(NW * NH * BM_R * BM_C + 255) / 256, 256>>>(mask, rpb, rel_idx);

    cudaFuncSetAttribute(win_attn_kernel,
                         cudaFuncAttributeMaxDynamicSharedMemorySize,
                         SMEM_U32 * sizeof(uint32_t));
    win_attn_kernel<<<B_TOT, 256, SMEM_U32 * sizeof(uint32_t)>>>(x, qkv_b, proj_b, out);
}

// round 12
// speedup vs baseline: 4.2980x; 1.0260x over previous
#include <cuda_runtime.h>
#include <cuda_fp16.h>
#include <cstdint>
#include <cstddef>

#define B_TOT 4096
#define NTOK  49
#define DIM   128
#define NH    4
#define HD    32
#define NW    64
#define SCALE 0.17677669529663687f   // 32^-0.5

// ---------------- device scratch ----------------
// fp16 weight B-fragments: per (kt, jt, lane) -> uint2 {b0, b1} (each = fp16x2)
__device__ uint2 g_wqkv16[8 * 48 * 32];
__device__ uint2 g_wproj16[8 * 16 * 32];
// bias+mask, padded: [NW][NH][64 rows][56 cols]; cols>=49 = -1e30, rows>=49 = 0
#define BM_R 64
#define BM_C 56
__device__ float g_bm[NW * NH * BM_R * BM_C];

// ---------------- helpers ----------------
__device__ __forceinline__ uint32_t pack_h2(float a, float b) {
    __half2 h = __floats2half2_rn(a, b);
    return *reinterpret_cast<uint32_t*>(&h);
}

__device__ __forceinline__ void mma_f16(float c[4],
                                        uint32_t a0, uint32_t a1, uint32_t a2, uint32_t a3,
                                        uint32_t b0, uint32_t b1) {
    asm volatile(
        "mma.sync.aligned.m16n8k16.row.col.f32.f16.f16.f32 "
        "{%0,%1,%2,%3}, {%4,%5,%6,%7}, {%8,%9}, {%0,%1,%2,%3};\n"
        : "+f"(c[0]), "+f"(c[1]), "+f"(c[2]), "+f"(c[3])
        : "r"(a0), "r"(a1), "r"(a2), "r"(a3), "r"(b0), "r"(b1));
}

// ---------------- prep kernels ----------------
__global__ void pack_w_kernel(const float* __restrict__ qkv_w,
                              const float* __restrict__ proj_w) {
    int idx = blockIdx.x * blockDim.x + threadIdx.x;
    if (idx < 8 * 48 * 32) {
        int kt   = idx / (48 * 32);
        int jt   = (idx / 32) % 48;
        int lane = idx % 32;
        int n    = jt * 8 + (lane >> 2);
        int k0   = kt * 16 + (lane & 3) * 2;
        uint2 v;
        v.x = pack_h2(qkv_w[n * DIM + k0],     qkv_w[n * DIM + k0 + 1]);
        v.y = pack_h2(qkv_w[n * DIM + k0 + 8], qkv_w[n * DIM + k0 + 9]);
        g_wqkv16[idx] = v;
    }
    if (idx < 8 * 16 * 32) {
        int kt   = idx / (16 * 32);
        int jt   = (idx / 32) % 16;
        int lane = idx % 32;
        int n    = jt * 8 + (lane >> 2);
        int k0   = kt * 16 + (lane & 3) * 2;
        uint2 v;
        v.x = pack_h2(proj_w[n * DIM + k0],     proj_w[n * DIM + k0 + 1]);
        v.y = pack_h2(proj_w[n * DIM + k0 + 8], proj_w[n * DIM + k0 + 9]);
        g_wproj16[idx] = v;
    }
}

__global__ void pack_bm_kernel(const float* __restrict__ mask,
                               const float* __restrict__ rpb,
                               const int*   __restrict__ rel_index) {
    int idx = blockIdx.x * blockDim.x + threadIdx.x;
    const int total = NW * NH * BM_R * BM_C;
    if (idx >= total) return;
    int col = idx % BM_C;
    int row = (idx / BM_C) % BM_R;
    int h   = (idx / (BM_C * BM_R)) % NH;
    int w   = idx / (BM_C * BM_R * NH);
    float v;
    if (row < NTOK && col < NTOK) {
        int r = row * NTOK + col;
        v = rpb[rel_index[r] * NH + h] + mask[w * NTOK * NTOK + r];
    } else if (row < NTOK) {
        v = -1e30f;        // pad column: exp -> 0
    } else {
        v = 0.f;           // pad row: discarded later
    }
    g_bm[idx] = v;
}

// ---------------- smem layout (uint32 units) ----------------
// XF @0      : 4096  x / attnout, A-frag-linear fp16  [64x128]
// QF @4096   : 4096  q per head, A-frag-linear fp16   [64x32] x4
// KF @8192   : 4096  k per head, B-frag-linear fp16   [n=64 tok][k=32 dim] x4
// VF @12288  : 4096  v per head, B-frag-linear fp16   [k=64 tok][n=32 dim] x4
#define XF 0
#define QF 4096
#define KF 8192
#define VF 12288
#define SMEM_U32 16384    // 65536 bytes; x3 CTAs = 192 KB/SM

extern __shared__ uint32_t smem_u32[];

// compute 2 jtiles of GEMM1 for this warp (acc[m][j][r])
__device__ __forceinline__ void gemm1_tiles(const uint32_t* sm, int lane, int jt0,
                                            float acc[4][2][4]) {
    #pragma unroll
    for (int m = 0; m < 4; m++)
        #pragma unroll
        for (int j = 0; j < 2; j++)
            #pragma unroll
            for (int r = 0; r < 4; r++) acc[m][j][r] = 0.f;

    #pragma unroll
    for (int kt = 0; kt < 8; ++kt) {
        uint4 af[4];
        #pragma unroll
        for (int m = 0; m < 4; m++)
            af[m] = *(const uint4*)(sm + XF + ((kt * 4 + m) * 32 + lane) * 4);
        #pragma unroll
        for (int j = 0; j < 2; j++) {
            uint2 bw = __ldg(&g_wqkv16[(kt * 48 + jt0 + j) * 32 + lane]);
            #pragma unroll
            for (int m = 0; m < 4; m++)
                mma_f16(acc[m][j], af[m].x, af[m].y, af[m].z, af[m].w, bw.x, bw.y);
        }
    }
}

__global__ void __launch_bounds__(256, 3)
win_attn_kernel(const float* __restrict__ x,
                const float* __restrict__ qkv_b,
                const float* __restrict__ proj_b,
                float* __restrict__ out) {
    const int b    = blockIdx.x;
    const int tid  = threadIdx.x;
    const int warp = tid >> 5;       // 0..7
    const int lane = tid & 31;
    const int g    = lane >> 2;
    const int tg   = lane & 3;

    uint32_t* sm  = smem_u32;
    char*     smb = reinterpret_cast<char*>(smem_u32);

    // load x into A-frag-linear fp16; pad rows (>=49) written as zero directly
    const float* xb = x + (size_t)b * (NTOK * DIM);
    #pragma unroll
    for (int i = tid; i < 64 * 64; i += 256) {
        int r  = i >> 6;
        int c2 = i & 63;
        int c  = c2 * 2;
        uint32_t val = 0u;
        if (r < NTOK) {
            float2 v = *(const float2*)(xb + r * DIM + c);
            val = pack_h2(v.x, v.y);
        }
        int kt   = c >> 4;
        int m    = r >> 4;
        int ln   = (r & 7) * 4 + (c2 & 3);
        int reg  = ((r >> 3) & 1) | (((c >> 3) & 1) << 1);
        sm[XF + ((kt * 4 + m) * 32 + ln) * 4 + reg] = val;
    }
    __syncthreads();

    // ---------- GEMM1: 3 passes x 2 jtiles/warp; pass 0=q, 1=k, 2=v ----------
    // pass 0: q
    {
        const int jt0 = warp * 2;            // 0..15
        float acc[4][2][4];
        gemm1_tiles(sm, lane, jt0, acc);
        #pragma unroll
        for (int j = 0; j < 2; j++) {
            int jbase = (jt0 + j) * 8;       // 0..127
            int h     = jbase >> 5;
            int cl    = (jbase & 31) + tg * 2;
            float b0f = __ldg(qkv_b + jbase + tg * 2);
            float b1f = __ldg(qkv_b + jbase + tg * 2 + 1);
            int ktq   = cl >> 4;
            int regc  = (cl >> 3) & 1;
            #pragma unroll
            for (int m = 0; m < 4; m++) {
                uint32_t base = QF + h * 1024 + ((ktq * 4 + m) * 32 + lane) * 4;
                sm[base + (regc << 1)]     = pack_h2((acc[m][j][0] + b0f) * SCALE,
                                                     (acc[m][j][1] + b1f) * SCALE);
                sm[base + 1 + (regc << 1)] = pack_h2((acc[m][j][2] + b0f) * SCALE,
                                                     (acc[m][j][3] + b1f) * SCALE);
            }
        }
    }
    // pass 1: k
    {
        const int jt0 = 16 + warp * 2;       // 16..31
        float acc[4][2][4];
        gemm1_tiles(sm, lane, jt0, acc);
        #pragma unroll
        for (int j = 0; j < 2; j++) {
            int jg    = (jt0 + j) * 8;       // global col 128..255
            int j2    = jg - 128;
            int h     = j2 >> 5;
            int cl    = (j2 & 31) + tg * 2;
            float b0f = __ldg(qkv_b + jg + tg * 2);
            float b1f = __ldg(qkv_b + jg + tg * 2 + 1);
            int ktk   = cl >> 4;
            int reg   = (cl >> 3) & 1;
            #pragma unroll
            for (int m = 0; m < 4; m++) {
                sm[KF + h * 1024 + ((ktk * 8 + 2 * m) * 32 + lane) * 2 + reg] =
                    pack_h2(acc[m][j][0] + b0f, acc[m][j][1] + b1f);
                sm[KF + h * 1024 + ((ktk * 8 + 2 * m + 1) * 32 + lane) * 2 + reg] =
                    pack_h2(acc[m][j][2] + b0f, acc[m][j][3] + b1f);
            }
        }
    }
    // pass 2: v
    {
        const int jt0 = 32 + warp * 2;       // 32..47
        float acc[4][2][4];
        gemm1_tiles(sm, lane, jt0, acc);
        #pragma unroll
        for (int j = 0; j < 2; j++) {
            int jg    = (jt0 + j) * 8;       // global col 256..383
            int j2    = jg - 256;
            int h     = j2 >> 5;
            int cl    = (j2 & 31) + tg * 2;
            float b0f = __ldg(qkv_b + jg + tg * 2);
            float b1f = __ldg(qkv_b + jg + tg * 2 + 1);
            #pragma unroll
            for (int m = 0; m < 4; m++) {
                #pragma unroll
                for (int rs = 0; rs < 2; rs++) {
                    int t = m * 16 + g + 8 * rs;
                    #pragma unroll
                    for (int cs = 0; cs < 2; cs++) {
                        int   d   = cl + cs;
                        float val = acc[m][j][rs * 2 + cs] + (cs ? b1f : b0f);
                        int ktv = t >> 4;
                        int nt  = d >> 3;
                        int ln  = (d & 7) * 4 + ((t & 7) >> 1);
                        int reg = (t >> 3) & 1;
                        uint32_t slot = VF + h * 1024 + ((ktv * 4 + nt) * 32 + ln) * 2 + reg;
                        *reinterpret_cast<__half*>(smb + slot * 4 + (t & 1) * 2) =
                            __float2half_rn(val);
                    }
                }
            }
        }
    }
    __syncthreads();

    // ---------- fused S = q@k^T -> softmax -> PV, 2 units/warp ----------
    // unit u = (head h = u>>2, m-tile mt = u&3): 16 complete score rows.
    #pragma unroll 1
    for (int u = warp; u < 16; u += 8) {
        const int h  = u >> 2;
        const int mt = u & 3;

        // S: acc[jt][0..1] = rows r0, cols jt*8+2tg+{0,1}; [2..3] = row r0+8
        float acc[7][4];
        #pragma unroll
        for (int jt = 0; jt < 7; jt++)
            #pragma unroll
            for (int r = 0; r < 4; r++) acc[jt][r] = 0.f;

        #pragma unroll
        for (int kt = 0; kt < 2; ++kt) {
            uint4 af = *(const uint4*)(sm + QF + h * 1024 + ((kt * 4 + mt) * 32 + lane) * 4);
            #pragma unroll
            for (int jt = 0; jt < 7; ++jt) {
                uint2 bw = *(const uint2*)(sm + KF + h * 1024 + ((kt * 8 + jt) * 32 + lane) * 2);
                mma_f16(acc[jt], af.x, af.y, af.z, af.w, bw.x, bw.y);
            }
        }

        // bias + mask (pad cols arrive as -1e30 from the table)
        const int r0 = mt * 16 + g;
        const float* bm = g_bm + ((size_t)(b & (NW - 1)) * NH + h) * (BM_R * BM_C);
        #pragma unroll
        for (int jt = 0; jt < 7; ++jt) {
            int c0 = jt * 8 + tg * 2;
            float2 bv0 = __ldg((const float2*)(bm + r0 * BM_C + c0));
            float2 bv1 = __ldg((const float2*)(bm + (r0 + 8) * BM_C + c0));
            acc[jt][0] += bv0.x; acc[jt][1] += bv0.y;
            acc[jt][2] += bv1.x; acc[jt][3] += bv1.y;
        }

        // row-wise softmax: reduce 14 locals + 2 shuffles over the tg quartet
        float mx0 = -1e30f, mx1 = -1e30f;
        #pragma unroll
        for (int jt = 0; jt < 7; ++jt) {
            mx0 = fmaxf(mx0, fmaxf(acc[jt][0], acc[jt][1]));
            mx1 = fmaxf(mx1, fmaxf(acc[jt][2], acc[jt][3]));
        }
        #pragma unroll
        for (int o = 1; o <= 2; o <<= 1) {
            mx0 = fmaxf(mx0, __shfl_xor_sync(0xffffffffu, mx0, o));
            mx1 = fmaxf(mx1, __shfl_xor_sync(0xffffffffu, mx1, o));
        }
        float s0 = 0.f, s1 = 0.f;
        #pragma unroll
        for (int jt = 0; jt < 7; ++jt) {
            acc[jt][0] = __expf(acc[jt][0] - mx0); s0 += acc[jt][0];
            acc[jt][1] = __expf(acc[jt][1] - mx0); s0 += acc[jt][1];
            acc[jt][2] = __expf(acc[jt][2] - mx1); s1 += acc[jt][2];
            acc[jt][3] = __expf(acc[jt][3] - mx1); s1 += acc[jt][3];
        }
        #pragma unroll
        for (int o = 1; o <= 2; o <<= 1) {
            s0 += __shfl_xor_sync(0xffffffffu, s0, o);
            s1 += __shfl_xor_sync(0xffffffffu, s1, o);
        }
        float i0 = 1.f / s0, i1 = 1.f / s1;

        // P -> fp16 pairs; S C-layout == PV A-layout, so no smem round-trip
        uint32_t ph[7][2];
        #pragma unroll
        for (int jt = 0; jt < 7; ++jt) {
            ph[jt][0] = pack_h2(acc[jt][0] * i0, acc[jt][1] * i0);
            ph[jt][1] = pack_h2(acc[jt][2] * i1, acc[jt][3] * i1);
        }

        // PV: attnout[16 x 32] = P[16 x 64pad] @ V[64pad x 32]
        float po[4][4];
        #pragma unroll
        for (int n = 0; n < 4; n++)
            #pragma unroll
            for (int r = 0; r < 4; r++) po[n][r] = 0.f;

        #pragma unroll
        for (int kt = 0; kt < 4; ++kt) {
            uint32_t a0 = ph[2 * kt][0], a1 = ph[2 * kt][1];
            uint32_t a2 = (kt < 3) ? ph[2 * kt + 1][0] : 0u;
            uint32_t a3 = (kt < 3) ? ph[2 * kt + 1][1] : 0u;
            #pragma unroll
            for (int n = 0; n < 4; ++n) {
                uint2 bw = *(const uint2*)(sm + VF + h * 1024 + ((kt * 4 + n) * 32 + lane) * 2);
                mma_f16(po[n], a0, a1, a2, a3, bw.x, bw.y);
            }
        }

        // scatter into A-frag-linear attnout (reuses XF)
        #pragma unroll
        for (int n = 0; n < 4; ++n) {
            int cg   = h * 32 + n * 8 + tg * 2;
            int ktx  = cg >> 4;
            int regc = (cg >> 3) & 1;
            uint32_t base = XF + ((ktx * 4 + mt) * 32 + lane) * 4;
            sm[base + (regc << 1)]     = pack_h2(po[n][0], po[n][1]);
            sm[base + 1 + (regc << 1)] = pack_h2(po[n][2], po[n][3]);
        }
    }
    __syncthreads();

    // ---------- GEMM3: out = attnout @ proj_w^T + proj_b, 2 jtiles/warp ------
    {
        float acc[2][4][4];
        #pragma unroll
        for (int jj = 0; jj < 2; jj++)
            #pragma unroll
            for (int m = 0; m < 4; m++)
                #pragma unroll
                for (int r = 0; r < 4; r++) acc[jj][m][r] = 0.f;

        #pragma unroll
        for (int kt = 0; kt < 8; ++kt) {
            uint4 af[4];
            #pragma unroll
            for (int m = 0; m < 4; m++)
                af[m] = *(const uint4*)(sm + XF + ((kt * 4 + m) * 32 + lane) * 4);
            #pragma unroll
            for (int jj = 0; jj < 2; jj++) {
                int jt = warp + jj * 8;
                uint2 bw = __ldg(&g_wproj16[(kt * 16 + jt) * 32 + lane]);
                #pragma unroll
                for (int m = 0; m < 4; m++)
                    mma_f16(acc[jj][m], af[m].x, af[m].y, af[m].z, af[m].w, bw.x, bw.y);
            }
        }

        float* ob = out + (size_t)b * (NTOK * DIM);
        #pragma unroll
        for (int jj = 0; jj < 2; jj++) {
            int jt = warp + jj * 8;
            int c0 = jt * 8 + tg * 2;
            float pb0 = __ldg(proj_b + c0);
            float pb1 = __ldg(proj_b + c0 + 1);
            #pragma unroll
            for (int m = 0; m < 4; m++) {
                int row = m * 16 + g;
                if (row < NTOK) {
                    float2 v; v.x = acc[jj][m][0] + pb0; v.y = acc[jj][m][1] + pb1;
                    *(float2*)(ob + row * DIM + c0) = v;
                }
                if (row + 8 < NTOK) {
                    float2 v; v.x = acc[jj][m][2] + pb0; v.y = acc[jj][m][3] + pb1;
                    *(float2*)(ob + (row + 8) * DIM + c0) = v;
                }
            }
        }
    }
}

// ---------------- launch ----------------
extern "C" void kernel_launch(void* const* d_in, const int* in_sizes, int n_in,
                              void* d_out, int out_size) {
    const float* x       = (const float*)d_in[0];
    const float* mask    = (const float*)d_in[1];
    const float* qkv_w   = (const float*)d_in[2];
    const float* qkv_b   = (const float*)d_in[3];
    const float* rpb     = (const float*)d_in[4];
    const float* proj_w  = (const float*)d_in[5];
    const float* proj_b  = (const float*)d_in[6];
    const int*   rel_idx = (const int*)d_in[7];
    float* out = (float*)d_out;

    pack_w_kernel<<<(8 * 48 * 32 + 255) / 256, 256>>>(qkv_w, proj_w);
    pack_bm_kernel<<<(NW * NH * BM_R * BM_C + 255) / 256, 256>>>(mask, rpb, rel_idx);

    cudaFuncSetAttribute(win_attn_kernel,
                         cudaFuncAttributeMaxDynamicSharedMemorySize,
                         SMEM_U32 * sizeof(uint32_t));
    win_attn_kernel<<<B_TOT, 256, SMEM_U32 * sizeof(uint32_t)>>>(x, qkv_b, proj_b, out);
}